// round 2
// baseline (speedup 1.0000x reference)
#include <cuda_runtime.h>
#include <math.h>

#define SQG 3.1464265445104548f   /* sqrt(NU-MU)=sqrt(9.9) */
#define SQ2 1.4142135623730951f

// ------------------- device scratch (static: no allocs) -------------------
__device__ float g_scale[9];
__device__ float g_c[9];
__device__ float g_part[9 * 64];
__device__ float g_Aq[1024 * 1024];
__device__ float g_Wq[1024 * 1024];
__device__ float g_ImAq[1024 * 1024];
__device__ float g_Xq[1024 * 1024];
__device__ float g_Xq2[1024 * 1024];
__device__ float g_Tq[1024 * 1024];
__device__ float g_Ar[7 * 512 * 512];
__device__ float g_Wr[8 * 512 * 512];
__device__ float g_ImAr[8 * 512 * 512];
__device__ float g_Xr[8 * 512 * 512];
__device__ float g_Xr2[8 * 512 * 512];
__device__ float g_Tr[8 * 512 * 512];
__device__ float g_P[8 * 512 * 512];
__device__ float g_Gs[7 * 512 * 512];
__device__ float g_Qm[4096 * 1024];
__device__ float g_xh[8192u * 4096u];
__device__ float g_act[8192u * 512u];
__device__ float g_h0[8192u * 512u];
__device__ float g_h1[8192u * 512u];
__device__ float g_yh[8192u * 4096u];

// ------------------- reductions: Frobenius norms -> scales -------------------
__global__ void red_in(const float* Fq, const float* Fr0, const float* Frr) {
    __shared__ float sh[256];
    int z = blockIdx.y;
    const float* p; long n;
    if (z == 0)      { p = Fq;  n = 4096L * 1024; }
    else if (z == 1) { p = Fr0; n = 512L * 512; }
    else             { p = Frr + (long)(z - 2) * 512 * 1024; n = 512L * 1024; }
    float s = 0.f;
    for (long i = (long)blockIdx.x * 256 + threadIdx.x; i < n; i += 64L * 256) {
        float v = p[i]; s += v * v;
    }
    sh[threadIdx.x] = s; __syncthreads();
    for (int o = 128; o > 0; o >>= 1) {
        if (threadIdx.x < o) sh[threadIdx.x] += sh[threadIdx.x + o];
        __syncthreads();
    }
    if (threadIdx.x == 0) g_part[z * 64 + blockIdx.x] = sh[0];
}
__global__ void red_in_fin(const float* fq, const float* fr) {
    int t = threadIdx.x;
    if (t < 9) {
        float s = 0.f;
        for (int i = 0; i < 64; i++) s += g_part[t * 64 + i];
        float f = (t == 0) ? fq[0] : fr[t - 1];
        g_scale[t] = f / (sqrtf(s) + 1e-5f);
    }
}
__global__ void red_w() {
    __shared__ float sh[256];
    int z = blockIdx.y;
    const float* p; long n;
    if (z == 0) { p = g_Wq; n = 1024L * 1024; }
    else        { p = g_Wr + (long)(z - 1) * 262144; n = 262144; }
    float s = 0.f;
    for (long i = (long)blockIdx.x * 256 + threadIdx.x; i < n; i += 64L * 256) {
        float v = p[i]; s += v * v;
    }
    sh[threadIdx.x] = s; __syncthreads();
    for (int o = 128; o > 0; o >>= 1) {
        if (threadIdx.x < o) sh[threadIdx.x] += sh[threadIdx.x + o];
        __syncthreads();
    }
    if (threadIdx.x == 0) g_part[z * 64 + blockIdx.x] = sh[0];
}
__global__ void red_w_fin() {
    int t = threadIdx.x;
    if (t < 9) {
        float s = 0.f;
        for (int i = 0; i < 64; i++) s += g_part[t * 64 + i];
        g_c[t] = 1.0f / s;
    }
}

// ------------------- elementwise prep -------------------
__global__ void prepQ(const float* Fq) {
    int e = blockIdx.x * 256 + threadIdx.x;      // < 1048576
    int i = e >> 10, j = e & 1023;
    float s = g_scale[0];
    float a = g_Aq[e] + s * (Fq[i * 1024 + j] - Fq[j * 1024 + i]);
    float d = (i == j) ? 1.f : 0.f;
    g_Wq[e] = d + a; g_ImAq[e] = d - a;
}
__global__ void prepR(const float* Fr0, const float* Frr) {
    int e = blockIdx.x * 256 + threadIdx.x;      // < 2097152
    int z = e >> 18; int r = e & 262143;
    int i = r >> 9, j = r & 511;
    float a;
    if (z == 0) {
        float s = g_scale[1];
        a = s * (Fr0[i * 512 + j] - Fr0[j * 512 + i]);
    } else {
        float s = g_scale[1 + z];
        const float* B = Frr + (long)(z - 1) * 524288;
        a = g_Ar[(long)(z - 1) * 262144 + r] + s * (B[j * 1024 + i] - B[i * 1024 + j]);
    }
    float d = (i == j) ? 1.f : 0.f;
    g_Wr[e] = d + a; g_ImAr[e] = d - a;
}
__global__ void transQ() {
    int e = blockIdx.x * 256 + threadIdx.x;
    int i = e >> 10, j = e & 1023;
    g_Xq[e] = g_c[0] * g_Wq[j * 1024 + i];
}
__global__ void transR() {
    int e = blockIdx.x * 256 + threadIdx.x;
    int z = e >> 18; int r = e & 262143;
    int i = r >> 9, j = r & 511;
    g_Xr[e] = g_c[1 + z] * g_Wr[z * 262144 + j * 512 + i];
}

// ------------------- generic tiled SGEMM with fused epilogues -------------------
struct GP {
    const float *A0, *A1, *B0, *B1, *E, *S1, *bias;
    float* C;
    int lda0, lda1, ldb0, ldb1, ldc, ld1;
    int M, N, K, ksplit;
    long sA, sB, sC, sE;
    int sIdx, sStride, sPow, epi;
    float aConst, c1;
};

// epi: 0 plain | 1: C=2E-acc | 2: relu(al*acc+bias[c]) | 3: al*acc-S1 | 4: S1-al*acc
//      5: al*acc + c1*S1 + bias[c]
template <int TA, int TB>
__global__ void __launch_bounds__(256) gemm_k(GP p) {
    int z = blockIdx.z;
    const float* A0 = p.A0 + (long)z * p.sA;
    const float* B0 = p.B0 + (long)z * p.sB;
    float* C = p.C + (long)z * p.sC;
    __shared__ float As[16][132];
    __shared__ float Bs[16][132];
    int bm = blockIdx.y * 128, bn = blockIdx.x * 128;
    int tid = threadIdx.x;
    int tx = tid & 15, ty = tid >> 4;
    float acc[8][8];
#pragma unroll
    for (int i = 0; i < 8; i++)
#pragma unroll
        for (int j = 0; j < 8; j++) acc[i][j] = 0.f;

    for (int k0 = 0; k0 < p.K; k0 += 16) {
        if (TA == 0) {
#pragma unroll
            for (int it = 0; it < 2; ++it) {
                int li = tid + it * 256;       // 0..511
                int r = li >> 2;
                int kq = (li & 3) * 4;
                int gk = k0 + kq;
                const float* Ap; int ld;
                if (gk < p.ksplit) { Ap = A0; ld = p.lda0; }
                else { Ap = p.A1; ld = p.lda1; gk -= p.ksplit; }
                float4 v = *(const float4*)(Ap + (long)(bm + r) * ld + gk);
                As[kq + 0][r] = v.x; As[kq + 1][r] = v.y;
                As[kq + 2][r] = v.z; As[kq + 3][r] = v.w;
            }
        } else {
#pragma unroll
            for (int it = 0; it < 2; ++it) {
                int li = tid + it * 256;
                int kr = li >> 5;
                int m4 = (li & 31) * 4;
                float4 v = *(const float4*)(A0 + (long)(k0 + kr) * p.lda0 + bm + m4);
                *(float4*)&As[kr][m4] = v;
            }
        }
        if (TB == 0) {
#pragma unroll
            for (int it = 0; it < 2; ++it) {
                int li = tid + it * 256;
                int kr = li >> 5;
                int n4 = (li & 31) * 4;
                int gk = k0 + kr;
                const float* Bp; int ld;
                if (gk < p.ksplit) { Bp = B0; ld = p.ldb0; }
                else { Bp = p.B1; ld = p.ldb1; gk -= p.ksplit; }
                float4 v = *(const float4*)(Bp + (long)gk * ld + bn + n4);
                *(float4*)&Bs[kr][n4] = v;
            }
        } else {
#pragma unroll
            for (int it = 0; it < 2; ++it) {
                int li = tid + it * 256;
                int r = li >> 2;
                int kq = (li & 3) * 4;
                float4 v = *(const float4*)(B0 + (long)(bn + r) * p.ldb0 + k0 + kq);
                Bs[kq + 0][r] = v.x; Bs[kq + 1][r] = v.y;
                Bs[kq + 2][r] = v.z; Bs[kq + 3][r] = v.w;
            }
        }
        __syncthreads();
#pragma unroll
        for (int kk = 0; kk < 16; ++kk) {
            float4 a0 = *(const float4*)&As[kk][ty * 8];
            float4 a1 = *(const float4*)&As[kk][ty * 8 + 4];
            float4 b0 = *(const float4*)&Bs[kk][tx * 8];
            float4 b1 = *(const float4*)&Bs[kk][tx * 8 + 4];
            float a[8] = {a0.x, a0.y, a0.z, a0.w, a1.x, a1.y, a1.z, a1.w};
            float bb[8] = {b0.x, b0.y, b0.z, b0.w, b1.x, b1.y, b1.z, b1.w};
#pragma unroll
            for (int i = 0; i < 8; i++)
#pragma unroll
                for (int j = 0; j < 8; j++)
                    acc[i][j] = fmaf(a[i], bb[j], acc[i][j]);
        }
        __syncthreads();
    }

    float al = p.aConst;
    if (p.sIdx >= 0) {
        float s = g_scale[p.sIdx + z * p.sStride];
        al *= (p.sPow == 2) ? s * s : s;
    }
    const float* E = (p.epi == 1) ? (p.E + (long)z * p.sE) : p.E;
#pragma unroll
    for (int i = 0; i < 8; i++) {
        int r = bm + ty * 8 + i;
#pragma unroll
        for (int j = 0; j < 8; j++) {
            int c = bn + tx * 8 + j;
            long ci = (long)r * p.ldc + c;
            float v = al * acc[i][j];
            switch (p.epi) {
                case 0: C[ci] = v; break;
                case 1: C[ci] = 2.f * E[ci] - v; break;
                case 2: C[ci] = fmaxf(v + p.bias[c], 0.f); break;
                case 3: C[ci] = v - p.S1[(long)r * p.ld1 + c]; break;
                case 4: C[ci] = p.S1[(long)r * p.ld1 + c] - v; break;
                case 5: C[ci] = v + p.c1 * p.S1[(long)r * p.ld1 + c] + p.bias[c]; break;
            }
        }
    }
}

// ------------------- host -------------------
static GP mk(const float* A, int lda, const float* B, int ldb, float* C, int ldc,
             int M, int N, int K) {
    GP p; memset(&p, 0, sizeof(p));
    p.A0 = A; p.lda0 = lda; p.B0 = B; p.ldb0 = ldb; p.C = C; p.ldc = ldc;
    p.M = M; p.N = N; p.K = K; p.ksplit = K; p.sIdx = -1; p.aConst = 1.f;
    return p;
}
static void G(int TA, int TB, const GP& p, int batch = 1) {
    dim3 g(p.N / 128, p.M / 128, batch);
    if (TA == 0 && TB == 0) gemm_k<0, 0><<<g, 256>>>(p);
    else if (TA == 0)       gemm_k<0, 1><<<g, 256>>>(p);
    else                    gemm_k<1, 0><<<g, 256>>>(p);
}
static float* sym(const void* s) {
    void* ptr = nullptr;
    cudaGetSymbolAddress(&ptr, s);
    return (float*)ptr;
}

extern "C" void kernel_launch(void* const* d_in, const int* in_sizes, int n_in,
                              void* d_out, int out_size) {
    const float* x   = (const float*)d_in[0];
    const float* Fq  = (const float*)d_in[1];
    const float* fq  = (const float*)d_in[2];
    const float* by  = (const float*)d_in[3];
    const float* Fr0 = (const float*)d_in[4];
    const float* Frr = (const float*)d_in[5];
    const float* fr  = (const float*)d_in[6];
    const float* b   = (const float*)d_in[7];
    float* out = (float*)d_out;

    float* Aq   = sym(g_Aq);
    float* Wq   = sym(g_Wq);
    float* ImAq = sym(g_ImAq);
    float* Xq   = sym(g_Xq);
    float* Xq2  = sym(g_Xq2);
    float* Tq   = sym(g_Tq);
    float* Arr  = sym(g_Ar);
    float* Wr   = sym(g_Wr);
    float* ImAr = sym(g_ImAr);
    float* Xr   = sym(g_Xr);
    float* Xr2  = sym(g_Xr2);
    float* Tr   = sym(g_Tr);
    float* Pm   = sym(g_P);
    float* Gsm  = sym(g_Gs);
    float* Qm   = sym(g_Qm);
    float* xh   = sym(g_xh);
    float* act  = sym(g_act);
    float* h0   = sym(g_h0);
    float* h1   = sym(g_h1);
    float* yh   = sym(g_yh);
    (void)Arr;

    // 1) scales
    red_in<<<dim3(64, 9), 256>>>(Fq, Fr0, Frr);
    red_in_fin<<<1, 32>>>(fq, fr);

    // 2) Aq = s0^2 * V^T V  (V = Fq[1024:], 3072x1024)
    { GP p = mk(Fq + 1048576, 1024, Fq + 1048576, 1024, Aq, 1024, 1024, 1024, 3072);
      p.sIdx = 0; p.sStride = 0; p.sPow = 2; G(1, 0, p); }
    // 3) Ar[z] = s^2 * B2 B2^T (batch 7), B2 = Fr_rest[z][:,512:]
    { GP p = mk(Frr + 512, 1024, Frr + 512, 1024, Arr, 512, 512, 512, 512);
      p.sA = 524288; p.sB = 524288; p.sC = 262144;
      p.sIdx = 2; p.sStride = 1; p.sPow = 2; G(0, 1, p, 7); }

    prepQ<<<4096, 256>>>(Fq);
    prepR<<<8192, 256>>>(Fr0, Frr);
    red_w<<<dim3(64, 9), 256>>>();
    red_w_fin<<<1, 32>>>();
    transQ<<<4096, 256>>>();
    transR<<<8192, 256>>>();

    // 4) Newton-Schulz for Q (20 iters)
    float *Xc = Xq, *Xn = Xq2;
    for (int it = 0; it < 20; ++it) {
        { GP p = mk(Wq, 1024, Xc, 1024, Tq, 1024, 1024, 1024, 1024); G(0, 0, p); }
        { GP p = mk(Xc, 1024, Tq, 1024, Xn, 1024, 1024, 1024, 1024);
          p.epi = 1; p.E = Xc; G(0, 0, p); }
        float* t = Xc; Xc = Xn; Xn = t;
    }
    // 5) Newton-Schulz for the 8 R matrices (batched, 20 iters)
    float *Yc = Xr, *Yn = Xr2;
    for (int it = 0; it < 20; ++it) {
        { GP p = mk(Wr, 512, Yc, 512, Tr, 512, 512, 512, 512);
          p.sA = p.sB = p.sC = 262144; G(0, 0, p, 8); }
        { GP p = mk(Yc, 512, Tr, 512, Yn, 512, 512, 512, 512);
          p.sA = p.sB = p.sC = 262144; p.epi = 1; p.E = Yc; p.sE = 262144;
          G(0, 0, p, 8); }
        float* t = Yc; Yc = Yn; Yn = t;
    }

    // 6) assemble Q = [X*(I-A); -2*s*V*X]
    { GP p = mk(Xc, 1024, ImAq, 1024, Qm, 1024, 1024, 1024, 1024); G(0, 0, p); }
    { GP p = mk(Fq + 1048576, 1024, Xc, 1024, Qm + 1048576, 1024, 3072, 1024, 1024);
      p.sIdx = 0; p.sStride = 0; p.sPow = 1; p.aConst = -2.f; G(0, 0, p); }
    // 7) P[z] = X*(I-A) (batch 8)
    { GP p = mk(Yc, 512, ImAr, 512, Pm, 512, 512, 512, 512);
      p.sA = p.sB = p.sC = 262144; G(0, 0, p, 8); }
    // 8) Gs[z] = -2*s*(B2^T X_{z+1}) (batch 7)
    { GP p = mk(Frr + 512, 1024, Yc + 262144, 512, Gsm, 512, 512, 512, 512);
      p.sA = 524288; p.sB = 262144; p.sC = 262144;
      p.sIdx = 2; p.sStride = 1; p.sPow = 1; p.aConst = -2.f; G(1, 0, p, 7); }

    // 9) xh = sqrt_gam * x @ Q^T
    { GP p = mk(x, 1024, Qm, 1024, xh, 4096, 8192, 4096, 1024);
      p.aConst = SQG; G(0, 1, p); }

    // 10) layer 0
    { GP p = mk(xh, 4096, Pm, 512, act, 512, 8192, 512, 512);
      p.aConst = SQ2; p.epi = 2; p.bias = b; G(0, 1, p); }
    { GP p = mk(act, 512, Pm, 512, h0, 512, 8192, 512, 512);
      p.aConst = SQ2; p.epi = 3; p.S1 = xh; p.ld1 = 4096; G(0, 0, p); }

    // 11) layers 1..7
    float* hb[2] = {h0, h1};
    for (int k = 1; k < 8; k++) {
        float* hp = hb[(k + 1) & 1];
        float* hn = hb[k & 1];
        const float* Pk = Pm + (long)k * 262144;
        const float* Gk = Gsm + (long)(k - 1) * 262144;
        { GP p = mk(xh + k * 512, 4096, Pk, 512, act, 512, 8192, 512, 1024);
          p.ksplit = 512; p.A1 = hp; p.lda1 = 512; p.B1 = Gk; p.ldb1 = 512;
          p.aConst = SQ2; p.epi = 2; p.bias = b + k * 512; G(0, 0, p); }
        { GP p = mk(act, 512, Pk, 512, (k == 7 ? yh + 3584 : hn),
                    (k == 7 ? 4096 : 512), 8192, 512, 512);
          p.aConst = SQ2; p.epi = 3; p.S1 = xh + k * 512; p.ld1 = 4096;
          G(0, 1, p); }
        { GP p = mk(act, 512, Gk, 512, yh + (k - 1) * 512, 4096, 8192, 512, 512);
          p.aConst = SQ2; p.epi = 4; p.S1 = hp; p.ld1 = 512; G(0, 1, p); }
    }

    // 12) out = 0.5*((MU+NU)*x + sqrt_gam * yh @ Q) + by
    { GP p = mk(yh, 4096, Qm, 1024, out, 1024, 8192, 1024, 4096);
      p.aConst = 0.5f * SQG; p.epi = 5; p.S1 = x; p.ld1 = 1024;
      p.c1 = 0.5f * (0.1f + 10.0f); p.bias = by; G(0, 0, p); }
}

// round 3
// speedup vs baseline: 1.4846x; 1.4846x over previous
#include <cuda_runtime.h>
#include <math.h>

#define SQG 3.1464265445104548f   /* sqrt(NU-MU)=sqrt(9.9) */
#define SQ2 1.4142135623730951f

// ------------------- device scratch (static: no allocs) -------------------
__device__ float g_scale[9];
__device__ float g_part[9 * 64];
__device__ float g_Aq[1024 * 1024];
__device__ float g_Wq[1024 * 1024];      // I+A -> inverse (in-place GJ)
__device__ float g_ImAq[1024 * 1024];
__device__ float g_Ar[7 * 512 * 512];
__device__ float g_Wr[8 * 512 * 512];    // I+A -> inverse (batched GJ)
__device__ float g_ImAr[8 * 512 * 512];
__device__ float g_DinvQ[64 * 64];
__device__ float g_CpanQ[1024 * 64];
__device__ float g_TQ[64 * 1024];
__device__ float g_DinvR[8 * 64 * 64];
__device__ float g_CpanR[8 * 512 * 64];
__device__ float g_TR[8 * 64 * 512];
__device__ float g_P[8 * 512 * 512];
__device__ float g_Gs[7 * 512 * 512];
__device__ float g_Qm[4096 * 1024];
__device__ float g_xh[8192u * 4096u];
__device__ float g_act[8192u * 512u];
__device__ float g_h0[8192u * 512u];
__device__ float g_h1[8192u * 512u];
__device__ float g_yh[8192u * 4096u];

// ------------------- reductions: Frobenius norms -> scales -------------------
__global__ void red_in(const float* Fq, const float* Fr0, const float* Frr) {
    __shared__ float sh[256];
    int z = blockIdx.y;
    const float* p; long n;
    if (z == 0)      { p = Fq;  n = 4096L * 1024; }
    else if (z == 1) { p = Fr0; n = 512L * 512; }
    else             { p = Frr + (long)(z - 2) * 512 * 1024; n = 512L * 1024; }
    float s = 0.f;
    for (long i = (long)blockIdx.x * 256 + threadIdx.x; i < n; i += 64L * 256) {
        float v = p[i]; s += v * v;
    }
    sh[threadIdx.x] = s; __syncthreads();
    for (int o = 128; o > 0; o >>= 1) {
        if (threadIdx.x < o) sh[threadIdx.x] += sh[threadIdx.x + o];
        __syncthreads();
    }
    if (threadIdx.x == 0) g_part[z * 64 + blockIdx.x] = sh[0];
}
__global__ void red_in_fin(const float* fq, const float* fr) {
    int t = threadIdx.x;
    if (t < 9) {
        float s = 0.f;
        for (int i = 0; i < 64; i++) s += g_part[t * 64 + i];
        float f = (t == 0) ? fq[0] : fr[t - 1];
        g_scale[t] = f / (sqrtf(s) + 1e-5f);
    }
}

// ------------------- elementwise prep -------------------
__global__ void prepQ(const float* Fq) {
    int e = blockIdx.x * 256 + threadIdx.x;      // < 1048576
    int i = e >> 10, j = e & 1023;
    float s = g_scale[0];
    float a = g_Aq[e] + s * (Fq[i * 1024 + j] - Fq[j * 1024 + i]);
    float d = (i == j) ? 1.f : 0.f;
    g_Wq[e] = d + a; g_ImAq[e] = d - a;
}
__global__ void prepR(const float* Fr0, const float* Frr) {
    int e = blockIdx.x * 256 + threadIdx.x;      // < 2097152
    int z = e >> 18; int r = e & 262143;
    int i = r >> 9, j = r & 511;
    float a;
    if (z == 0) {
        float s = g_scale[1];
        a = s * (Fr0[i * 512 + j] - Fr0[j * 512 + i]);
    } else {
        float s = g_scale[1 + z];
        const float* B = Frr + (long)(z - 1) * 524288;
        a = g_Ar[(long)(z - 1) * 262144 + r] + s * (B[j * 1024 + i] - B[i * 1024 + j]);
    }
    float d = (i == j) ? 1.f : 0.f;
    g_Wr[e] = d + a; g_ImAr[e] = d - a;
}

// ------------------- blocked in-place Gauss-Jordan (block 64, no pivot) -----
// step s:  Dinv = inv(W[s,s]);  T[:,j] = Dinv*W[s,j] (j!=s), T[:,s] = Dinv;
//          Cpan = old column panel W[:,s];
//          rows i!=s: W[i,j] -= Cpan_i*T[:,j] (j!=s), W[i,s] = -Cpan_i*T[:,s];
//          row  s:   W[s,:] = T.
__global__ void gj_diag(float* W, int n, int s, float* Dinv, float* Cpan,
                        long sW, long sD, long sC) {
    int z = blockIdx.x;
    W += (long)z * sW; Dinv += (long)z * sD; Cpan += (long)z * sC;
    int t = threadIdx.x;
    // save old column panel
    for (int e = t; e < n * 64; e += 256) {
        int i = e >> 6, c = e & 63;
        Cpan[e] = W[(long)i * n + s * 64 + c];
    }
    __shared__ float sh[64][65];
    for (int e = t; e < 4096; e += 256) {
        int i = e >> 6, j = e & 63;
        sh[i][j] = W[(long)(s * 64 + i) * n + s * 64 + j];
    }
    __syncthreads();
    int jc = t & 63, rb = (t >> 6) * 16;
    for (int p = 0; p < 64; p++) {
        float d = 1.0f / sh[p][p];
        float c[16];
#pragma unroll
        for (int r = 0; r < 16; r++) c[r] = sh[rb + r][p];
        float pv = sh[p][jc];
        __syncthreads();
        float npv = (jc == p) ? d : pv * d;   // new row-p value at col jc
#pragma unroll
        for (int r = 0; r < 16; r++) {
            int i = rb + r;
            if (i == p)           sh[i][jc] = npv;
            else if (jc == p)     sh[i][jc] = -c[r] * d;
            else                  sh[i][jc] = sh[i][jc] - c[r] * npv;
        }
        __syncthreads();
    }
    for (int e = t; e < 4096; e += 256) Dinv[e] = sh[e >> 6][e & 63];
}

__global__ void gj_row(const float* W, int n, int s, const float* Dinv, float* T,
                       long sW, long sD, long sT) {
    int z = blockIdx.y;
    W += (long)z * sW; Dinv += (long)z * sD; T += (long)z * sT;
    int jb = blockIdx.x;
    int t = threadIdx.x;
    if (jb == s) {
        for (int e = t; e < 4096; e += 256)
            T[(long)(e >> 6) * n + s * 64 + (e & 63)] = Dinv[e];
        return;
    }
    __shared__ float shD[64][65], shW[64][65];
    for (int e = t; e < 4096; e += 256) {
        int i = e >> 6, j = e & 63;
        shD[i][j] = Dinv[e];
        shW[i][j] = W[(long)(s * 64 + i) * n + jb * 64 + j];
    }
    __syncthreads();
    int jc = t & 63, rb = (t >> 6) * 16;
    float acc[16];
#pragma unroll
    for (int r = 0; r < 16; r++) acc[r] = 0.f;
    for (int k = 0; k < 64; k++) {
        float bv = shW[k][jc];
#pragma unroll
        for (int r = 0; r < 16; r++) acc[r] = fmaf(shD[rb + r][k], bv, acc[r]);
    }
#pragma unroll
    for (int r = 0; r < 16; r++)
        T[(long)(rb + r) * n + jb * 64 + jc] = acc[r];
}

__global__ void gj_upd(float* W, int n, int s, const float* Cpan, const float* T,
                       long sW, long sC, long sT) {
    int z = blockIdx.z;
    W += (long)z * sW; Cpan += (long)z * sC; T += (long)z * sT;
    int jb = blockIdx.x, ib = blockIdx.y;
    int t = threadIdx.x;
    if (ib == s) {   // write row panel from T
        for (int e = t; e < 4096; e += 256) {
            int i = e >> 6, j = e & 63;
            W[(long)(s * 64 + i) * n + jb * 64 + j] = T[(long)i * n + jb * 64 + j];
        }
        return;
    }
    __shared__ float shC[64][65], shT[64][65];
    for (int e = t; e < 4096; e += 256) {
        int i = e >> 6, j = e & 63;
        shC[i][j] = Cpan[(long)(ib * 64 + i) * 64 + j];
        shT[i][j] = T[(long)i * n + jb * 64 + j];
    }
    __syncthreads();
    int jc = t & 63, rb = (t >> 6) * 16;
    float acc[16];
#pragma unroll
    for (int r = 0; r < 16; r++) acc[r] = 0.f;
    for (int k = 0; k < 64; k++) {
        float tv = shT[k][jc];
#pragma unroll
        for (int r = 0; r < 16; r++) acc[r] = fmaf(shC[rb + r][k], tv, acc[r]);
    }
#pragma unroll
    for (int r = 0; r < 16; r++) {
        long idx = (long)(ib * 64 + rb + r) * n + jb * 64 + jc;
        float oldv = (jb == s) ? 0.f : W[idx];
        W[idx] = oldv - acc[r];
    }
}

// ------------------- generic tiled SGEMM with fused epilogues -------------------
struct GP {
    const float *A0, *A1, *B0, *B1, *E, *S1, *bias;
    float* C;
    int lda0, lda1, ldb0, ldb1, ldc, ld1;
    int M, N, K, ksplit;
    long sA, sB, sC, sE;
    int sIdx, sStride, sPow, epi;
    float aConst, c1;
};

// epi: 0 plain | 2: relu(al*acc+bias[c]) | 3: al*acc-S1 | 4: S1-al*acc
//      5: al*acc + c1*S1 + bias[c]
template <int TA, int TB>
__global__ void __launch_bounds__(256) gemm_k(GP p) {
    int z = blockIdx.z;
    const float* A0 = p.A0 + (long)z * p.sA;
    const float* B0 = p.B0 + (long)z * p.sB;
    float* C = p.C + (long)z * p.sC;
    __shared__ float As[16][132];
    __shared__ float Bs[16][132];
    int bm = blockIdx.y * 128, bn = blockIdx.x * 128;
    int tid = threadIdx.x;
    int tx = tid & 15, ty = tid >> 4;
    float acc[8][8];
#pragma unroll
    for (int i = 0; i < 8; i++)
#pragma unroll
        for (int j = 0; j < 8; j++) acc[i][j] = 0.f;

    for (int k0 = 0; k0 < p.K; k0 += 16) {
        if (TA == 0) {
#pragma unroll
            for (int it = 0; it < 2; ++it) {
                int li = tid + it * 256;       // 0..511
                int r = li >> 2;
                int kq = (li & 3) * 4;
                int gk = k0 + kq;
                const float* Ap; int ld;
                if (gk < p.ksplit) { Ap = A0; ld = p.lda0; }
                else { Ap = p.A1; ld = p.lda1; gk -= p.ksplit; }
                float4 v = *(const float4*)(Ap + (long)(bm + r) * ld + gk);
                As[kq + 0][r] = v.x; As[kq + 1][r] = v.y;
                As[kq + 2][r] = v.z; As[kq + 3][r] = v.w;
            }
        } else {
#pragma unroll
            for (int it = 0; it < 2; ++it) {
                int li = tid + it * 256;
                int kr = li >> 5;
                int m4 = (li & 31) * 4;
                float4 v = *(const float4*)(A0 + (long)(k0 + kr) * p.lda0 + bm + m4);
                *(float4*)&As[kr][m4] = v;
            }
        }
        if (TB == 0) {
#pragma unroll
            for (int it = 0; it < 2; ++it) {
                int li = tid + it * 256;
                int kr = li >> 5;
                int n4 = (li & 31) * 4;
                int gk = k0 + kr;
                const float* Bp; int ld;
                if (gk < p.ksplit) { Bp = B0; ld = p.ldb0; }
                else { Bp = p.B1; ld = p.ldb1; gk -= p.ksplit; }
                float4 v = *(const float4*)(Bp + (long)gk * ld + bn + n4);
                *(float4*)&Bs[kr][n4] = v;
            }
        } else {
#pragma unroll
            for (int it = 0; it < 2; ++it) {
                int li = tid + it * 256;
                int r = li >> 2;
                int kq = (li & 3) * 4;
                float4 v = *(const float4*)(B0 + (long)(bn + r) * p.ldb0 + k0 + kq);
                Bs[kq + 0][r] = v.x; Bs[kq + 1][r] = v.y;
                Bs[kq + 2][r] = v.z; Bs[kq + 3][r] = v.w;
            }
        }
        __syncthreads();
#pragma unroll
        for (int kk = 0; kk < 16; ++kk) {
            float4 a0 = *(const float4*)&As[kk][ty * 8];
            float4 a1 = *(const float4*)&As[kk][ty * 8 + 4];
            float4 b0 = *(const float4*)&Bs[kk][tx * 8];
            float4 b1 = *(const float4*)&Bs[kk][tx * 8 + 4];
            float a[8] = {a0.x, a0.y, a0.z, a0.w, a1.x, a1.y, a1.z, a1.w};
            float bb[8] = {b0.x, b0.y, b0.z, b0.w, b1.x, b1.y, b1.z, b1.w};
#pragma unroll
            for (int i = 0; i < 8; i++)
#pragma unroll
                for (int j = 0; j < 8; j++)
                    acc[i][j] = fmaf(a[i], bb[j], acc[i][j]);
        }
        __syncthreads();
    }

    float al = p.aConst;
    if (p.sIdx >= 0) {
        float s = g_scale[p.sIdx + z * p.sStride];
        al *= (p.sPow == 2) ? s * s : s;
    }
#pragma unroll
    for (int i = 0; i < 8; i++) {
        int r = bm + ty * 8 + i;
#pragma unroll
        for (int j = 0; j < 8; j++) {
            int c = bn + tx * 8 + j;
            long ci = (long)r * p.ldc + c;
            float v = al * acc[i][j];
            switch (p.epi) {
                case 0: C[ci] = v; break;
                case 2: C[ci] = fmaxf(v + p.bias[c], 0.f); break;
                case 3: C[ci] = v - p.S1[(long)r * p.ld1 + c]; break;
                case 4: C[ci] = p.S1[(long)r * p.ld1 + c] - v; break;
                case 5: C[ci] = v + p.c1 * p.S1[(long)r * p.ld1 + c] + p.bias[c]; break;
            }
        }
    }
}

// ------------------- host -------------------
static GP mk(const float* A, int lda, const float* B, int ldb, float* C, int ldc,
             int M, int N, int K) {
    GP p; memset(&p, 0, sizeof(p));
    p.A0 = A; p.lda0 = lda; p.B0 = B; p.ldb0 = ldb; p.C = C; p.ldc = ldc;
    p.M = M; p.N = N; p.K = K; p.ksplit = K; p.sIdx = -1; p.aConst = 1.f;
    return p;
}
static void G(int TA, int TB, const GP& p, int batch = 1) {
    dim3 g(p.N / 128, p.M / 128, batch);
    if (TA == 0 && TB == 0) gemm_k<0, 0><<<g, 256>>>(p);
    else if (TA == 0)       gemm_k<0, 1><<<g, 256>>>(p);
    else                    gemm_k<1, 0><<<g, 256>>>(p);
}
static float* sym(const void* s) {
    void* ptr = nullptr;
    cudaGetSymbolAddress(&ptr, s);
    return (float*)ptr;
}

extern "C" void kernel_launch(void* const* d_in, const int* in_sizes, int n_in,
                              void* d_out, int out_size) {
    const float* x   = (const float*)d_in[0];
    const float* Fq  = (const float*)d_in[1];
    const float* fq  = (const float*)d_in[2];
    const float* by  = (const float*)d_in[3];
    const float* Fr0 = (const float*)d_in[4];
    const float* Frr = (const float*)d_in[5];
    const float* fr  = (const float*)d_in[6];
    const float* b   = (const float*)d_in[7];
    float* out = (float*)d_out;

    float* Aq    = sym(g_Aq);
    float* Wq    = sym(g_Wq);
    float* ImAq  = sym(g_ImAq);
    float* Arr   = sym(g_Ar);
    float* Wr    = sym(g_Wr);
    float* ImAr  = sym(g_ImAr);
    float* DinvQ = sym(g_DinvQ);
    float* CpanQ = sym(g_CpanQ);
    float* TQ    = sym(g_TQ);
    float* DinvR = sym(g_DinvR);
    float* CpanR = sym(g_CpanR);
    float* TR    = sym(g_TR);
    float* Pm    = sym(g_P);
    float* Gsm   = sym(g_Gs);
    float* Qm    = sym(g_Qm);
    float* xh    = sym(g_xh);
    float* act   = sym(g_act);
    float* h0    = sym(g_h0);
    float* h1    = sym(g_h1);
    float* yh    = sym(g_yh);

    // 1) scales
    red_in<<<dim3(64, 9), 256>>>(Fq, Fr0, Frr);
    red_in_fin<<<1, 32>>>(fq, fr);

    // 2) Aq = s0^2 * V^T V  (V = Fq[1024:], 3072x1024)
    { GP p = mk(Fq + 1048576, 1024, Fq + 1048576, 1024, Aq, 1024, 1024, 1024, 3072);
      p.sIdx = 0; p.sStride = 0; p.sPow = 2; G(1, 0, p); }
    // 3) Ar[z] = s^2 * B2 B2^T (batch 7), B2 = Fr_rest[z][:,512:]
    { GP p = mk(Frr + 512, 1024, Frr + 512, 1024, Arr, 512, 512, 512, 512);
      p.sA = 524288; p.sB = 524288; p.sC = 262144;
      p.sIdx = 2; p.sStride = 1; p.sPow = 2; G(0, 1, p, 7); }

    prepQ<<<4096, 256>>>(Fq);
    prepR<<<8192, 256>>>(Fr0, Frr);

    // 4) invert Wq (1024x1024) by blocked GJ, 16 steps
    for (int s = 0; s < 16; s++) {
        gj_diag<<<1, 256>>>(Wq, 1024, s, DinvQ, CpanQ, 0, 0, 0);
        gj_row<<<dim3(16, 1), 256>>>(Wq, 1024, s, DinvQ, TQ, 0, 0, 0);
        gj_upd<<<dim3(16, 16, 1), 256>>>(Wq, 1024, s, CpanQ, TQ, 0, 0, 0);
    }
    // 5) invert the 8 Wr (512x512) by batched blocked GJ, 8 steps
    for (int s = 0; s < 8; s++) {
        gj_diag<<<8, 256>>>(Wr, 512, s, DinvR, CpanR, 262144, 4096, 32768);
        gj_row<<<dim3(8, 8), 256>>>(Wr, 512, s, DinvR, TR, 262144, 4096, 32768);
        gj_upd<<<dim3(8, 8, 8), 256>>>(Wr, 512, s, CpanR, TR, 262144, 32768, 32768);
    }

    // 6) assemble Q = [Winv*(I-A); -2*s*V*Winv]
    { GP p = mk(Wq, 1024, ImAq, 1024, Qm, 1024, 1024, 1024, 1024); G(0, 0, p); }
    { GP p = mk(Fq + 1048576, 1024, Wq, 1024, Qm + 1048576, 1024, 3072, 1024, 1024);
      p.sIdx = 0; p.sStride = 0; p.sPow = 1; p.aConst = -2.f; G(0, 0, p); }
    // 7) P[z] = Winv*(I-A) (batch 8)
    { GP p = mk(Wr, 512, ImAr, 512, Pm, 512, 512, 512, 512);
      p.sA = p.sB = p.sC = 262144; G(0, 0, p, 8); }
    // 8) Gs[z] = -2*s*(B2^T Winv_{z+1}) (batch 7)
    { GP p = mk(Frr + 512, 1024, Wr + 262144, 512, Gsm, 512, 512, 512, 512);
      p.sA = 524288; p.sB = 262144; p.sC = 262144;
      p.sIdx = 2; p.sStride = 1; p.sPow = 1; p.aConst = -2.f; G(1, 0, p, 7); }

    // 9) xh = sqrt_gam * x @ Q^T
    { GP p = mk(x, 1024, Qm, 1024, xh, 4096, 8192, 4096, 1024);
      p.aConst = SQG; G(0, 1, p); }

    // 10) layer 0
    { GP p = mk(xh, 4096, Pm, 512, act, 512, 8192, 512, 512);
      p.aConst = SQ2; p.epi = 2; p.bias = b; G(0, 1, p); }
    { GP p = mk(act, 512, Pm, 512, h0, 512, 8192, 512, 512);
      p.aConst = SQ2; p.epi = 3; p.S1 = xh; p.ld1 = 4096; G(0, 0, p); }

    // 11) layers 1..7
    float* hb[2] = {h0, h1};
    for (int k = 1; k < 8; k++) {
        float* hp = hb[(k + 1) & 1];
        float* hn = hb[k & 1];
        const float* Pk = Pm + (long)k * 262144;
        const float* Gk = Gsm + (long)(k - 1) * 262144;
        { GP p = mk(xh + k * 512, 4096, Pk, 512, act, 512, 8192, 512, 1024);
          p.ksplit = 512; p.A1 = hp; p.lda1 = 512; p.B1 = Gk; p.ldb1 = 512;
          p.aConst = SQ2; p.epi = 2; p.bias = b + k * 512; G(0, 0, p); }
        { GP p = mk(act, 512, Pk, 512, (k == 7 ? yh + 3584 : hn),
                    (k == 7 ? 4096 : 512), 8192, 512, 512);
          p.aConst = SQ2; p.epi = 3; p.S1 = xh + k * 512; p.ld1 = 4096;
          G(0, 1, p); }
        { GP p = mk(act, 512, Gk, 512, yh + (k - 1) * 512, 4096, 8192, 512, 512);
          p.aConst = SQ2; p.epi = 4; p.S1 = hp; p.ld1 = 512; G(0, 1, p); }
    }

    // 12) out = 0.5*((MU+NU)*x + sqrt_gam * yh @ Q) + by
    { GP p = mk(yh, 4096, Qm, 1024, out, 1024, 8192, 1024, 4096);
      p.aConst = 0.5f * SQG; p.epi = 5; p.S1 = x; p.ld1 = 1024;
      p.c1 = 0.5f * (0.1f + 10.0f); p.bias = by; G(0, 0, p); }
}

// round 5
// speedup vs baseline: 2.1935x; 1.4775x over previous
#include <cuda_runtime.h>
#include <cuda_bf16.h>
#include <math.h>
#include <stdint.h>

#define SQG 3.1464265445104548f   /* sqrt(NU-MU)=sqrt(9.9) */
#define SQ2 1.4142135623730951f

// ==================== device scratch ====================
__device__ float g_scale[9];
__device__ float g_part[9 * 64];
__device__ float g_Aq[1024 * 1024];
__device__ float g_Wq[1024 * 1024];
__device__ float g_ImAq[1024 * 1024];
__device__ float g_Ar[7 * 512 * 512];
__device__ float g_Wr[8 * 512 * 512];
__device__ float g_ImAr[8 * 512 * 512];
__device__ float g_DinvQ[64 * 64];
__device__ float g_CpanQ[1024 * 64];
__device__ float g_TQ[64 * 1024];
__device__ float g_DinvR[8 * 64 * 64];
__device__ float g_CpanR[8 * 512 * 64];
__device__ float g_TR[8 * 64 * 512];
__device__ float g_P[8 * 512 * 512];
__device__ float g_Gs[7 * 512 * 512];
__device__ float g_PT[8 * 512 * 512];
__device__ float g_GT[7 * 512 * 512];
__device__ float g_Qm[4096 * 1024];
__device__ float g_QmT[1024 * 4096];
__device__ float g_xh[8192u * 4096u];
__device__ float g_act[8192u * 512u];
__device__ float g_h0[8192u * 512u];
__device__ float g_h1[8192u * 512u];
__device__ float g_yh[8192u * 4096u];

// ==================== reductions ====================
__global__ void red_in(const float* Fq, const float* Fr0, const float* Frr) {
    __shared__ float sh[256];
    int z = blockIdx.y;
    const float* p; long n;
    if (z == 0)      { p = Fq;  n = 4096L * 1024; }
    else if (z == 1) { p = Fr0; n = 512L * 512; }
    else             { p = Frr + (long)(z - 2) * 512 * 1024; n = 512L * 1024; }
    float s = 0.f;
    for (long i = (long)blockIdx.x * 256 + threadIdx.x; i < n; i += 64L * 256) {
        float v = p[i]; s += v * v;
    }
    sh[threadIdx.x] = s; __syncthreads();
    for (int o = 128; o > 0; o >>= 1) {
        if (threadIdx.x < o) sh[threadIdx.x] += sh[threadIdx.x + o];
        __syncthreads();
    }
    if (threadIdx.x == 0) g_part[z * 64 + blockIdx.x] = sh[0];
}
__global__ void red_in_fin(const float* fq, const float* fr) {
    int t = threadIdx.x;
    if (t < 9) {
        float s = 0.f;
        for (int i = 0; i < 64; i++) s += g_part[t * 64 + i];
        float f = (t == 0) ? fq[0] : fr[t - 1];
        g_scale[t] = f / (sqrtf(s) + 1e-5f);
    }
}

// ==================== elementwise prep ====================
__global__ void prepQ(const float* Fq) {
    int e = blockIdx.x * 256 + threadIdx.x;
    int i = e >> 10, j = e & 1023;
    float s = g_scale[0];
    float a = g_Aq[e] + s * (Fq[i * 1024 + j] - Fq[j * 1024 + i]);
    float d = (i == j) ? 1.f : 0.f;
    g_Wq[e] = d + a; g_ImAq[e] = d - a;
}
__global__ void prepR(const float* Fr0, const float* Frr) {
    int e = blockIdx.x * 256 + threadIdx.x;
    int z = e >> 18; int r = e & 262143;
    int i = r >> 9, j = r & 511;
    float a;
    if (z == 0) {
        float s = g_scale[1];
        a = s * (Fr0[i * 512 + j] - Fr0[j * 512 + i]);
    } else {
        float s = g_scale[1 + z];
        const float* B = Frr + (long)(z - 1) * 524288;
        a = g_Ar[(long)(z - 1) * 262144 + r] + s * (B[j * 1024 + i] - B[i * 1024 + j]);
    }
    float d = (i == j) ? 1.f : 0.f;
    g_Wr[e] = d + a; g_ImAr[e] = d - a;
}

// ==================== transpose ====================
__global__ void tr_k(const float* src, float* dst, int R, int C, long sS, long sD) {
    int z = blockIdx.z;
    src += (long)z * sS; dst += (long)z * sD;
    __shared__ float t[32][33];
    int r0 = blockIdx.y * 32, c0 = blockIdx.x * 32;
    int tx = threadIdx.x & 31, ty = threadIdx.x >> 5;
    for (int i = ty; i < 32; i += 8) t[i][tx] = src[(long)(r0 + i) * C + c0 + tx];
    __syncthreads();
    for (int i = ty; i < 32; i += 8) dst[(long)(c0 + i) * R + r0 + tx] = t[tx][i];
}

// ==================== blocked in-place Gauss-Jordan (block 64) ====================
__global__ void gj_diag(float* W, int n, int s, float* Dinv, float* Cpan,
                        long sW, long sD, long sC) {
    int z = blockIdx.x;
    W += (long)z * sW; Dinv += (long)z * sD; Cpan += (long)z * sC;
    int t = threadIdx.x;
    for (int e = t; e < n * 64; e += 256) {
        int i = e >> 6, c = e & 63;
        Cpan[e] = W[(long)i * n + s * 64 + c];
    }
    __shared__ float sh[64][65];
    for (int e = t; e < 4096; e += 256) {
        int i = e >> 6, j = e & 63;
        sh[i][j] = W[(long)(s * 64 + i) * n + s * 64 + j];
    }
    __syncthreads();
    int jc = t & 63, rb = (t >> 6) * 16;
    for (int p = 0; p < 64; p++) {
        float d = 1.0f / sh[p][p];
        float c[16];
#pragma unroll
        for (int r = 0; r < 16; r++) c[r] = sh[rb + r][p];
        float pv = sh[p][jc];
        __syncthreads();
        float npv = (jc == p) ? d : pv * d;
#pragma unroll
        for (int r = 0; r < 16; r++) {
            int i = rb + r;
            if (i == p)       sh[i][jc] = npv;
            else if (jc == p) sh[i][jc] = -c[r] * d;
            else              sh[i][jc] = sh[i][jc] - c[r] * npv;
        }
        __syncthreads();
    }
    for (int e = t; e < 4096; e += 256) Dinv[e] = sh[e >> 6][e & 63];
}
__global__ void gj_row(const float* W, int n, int s, const float* Dinv, float* T,
                       long sW, long sD, long sT) {
    int z = blockIdx.y;
    W += (long)z * sW; Dinv += (long)z * sD; T += (long)z * sT;
    int jb = blockIdx.x;
    int t = threadIdx.x;
    if (jb == s) {
        for (int e = t; e < 4096; e += 256)
            T[(long)(e >> 6) * n + s * 64 + (e & 63)] = Dinv[e];
        return;
    }
    __shared__ float shD[64][65], shW[64][65];
    for (int e = t; e < 4096; e += 256) {
        int i = e >> 6, j = e & 63;
        shD[i][j] = Dinv[e];
        shW[i][j] = W[(long)(s * 64 + i) * n + jb * 64 + j];
    }
    __syncthreads();
    int jc = t & 63, rb = (t >> 6) * 16;
    float acc[16];
#pragma unroll
    for (int r = 0; r < 16; r++) acc[r] = 0.f;
    for (int k = 0; k < 64; k++) {
        float bv = shW[k][jc];
#pragma unroll
        for (int r = 0; r < 16; r++) acc[r] = fmaf(shD[rb + r][k], bv, acc[r]);
    }
#pragma unroll
    for (int r = 0; r < 16; r++)
        T[(long)(rb + r) * n + jb * 64 + jc] = acc[r];
}
__global__ void gj_upd(float* W, int n, int s, const float* Cpan, const float* T,
                       long sW, long sC, long sT) {
    int z = blockIdx.z;
    W += (long)z * sW; Cpan += (long)z * sC; T += (long)z * sT;
    int jb = blockIdx.x, ib = blockIdx.y;
    int t = threadIdx.x;
    if (ib == s) {
        for (int e = t; e < 4096; e += 256) {
            int i = e >> 6, j = e & 63;
            W[(long)(s * 64 + i) * n + jb * 64 + j] = T[(long)i * n + jb * 64 + j];
        }
        return;
    }
    __shared__ float shC[64][65], shT[64][65];
    for (int e = t; e < 4096; e += 256) {
        int i = e >> 6, j = e & 63;
        shC[i][j] = Cpan[(long)(ib * 64 + i) * 64 + j];
        shT[i][j] = T[(long)i * n + jb * 64 + j];
    }
    __syncthreads();
    int jc = t & 63, rb = (t >> 6) * 16;
    float acc[16];
#pragma unroll
    for (int r = 0; r < 16; r++) acc[r] = 0.f;
    for (int k = 0; k < 64; k++) {
        float tv = shT[k][jc];
#pragma unroll
        for (int r = 0; r < 16; r++) acc[r] = fmaf(shC[rb + r][k], tv, acc[r]);
    }
#pragma unroll
    for (int r = 0; r < 16; r++) {
        long idx = (long)(ib * 64 + rb + r) * n + jb * 64 + jc;
        float oldv = (jb == s) ? 0.f : W[idx];
        W[idx] = oldv - acc[r];
    }
}

// ==================== SIMT GEMM (setup only) ====================
struct GP {
    const float *A0, *A1, *B0, *B1, *S1, *bias;
    float* C;
    int lda0, lda1, ldb0, ldb1, ldc, ld1;
    int M, N, K, ksplit;
    long sA, sB, sC;
    int sIdx, sStride, sPow, epi;
    float aConst, c1;
};
template <int TA, int TB>
__global__ void __launch_bounds__(256) gemm_k(GP p) {
    int z = blockIdx.z;
    const float* A0 = p.A0 + (long)z * p.sA;
    const float* B0 = p.B0 + (long)z * p.sB;
    float* C = p.C + (long)z * p.sC;
    __shared__ float As[16][132];
    __shared__ float Bs[16][132];
    int bm = blockIdx.y * 128, bn = blockIdx.x * 128;
    int tid = threadIdx.x;
    int tx = tid & 15, ty = tid >> 4;
    float acc[8][8];
#pragma unroll
    for (int i = 0; i < 8; i++)
#pragma unroll
        for (int j = 0; j < 8; j++) acc[i][j] = 0.f;

    for (int k0 = 0; k0 < p.K; k0 += 16) {
        if (TA == 0) {
#pragma unroll
            for (int it = 0; it < 2; ++it) {
                int li = tid + it * 256;
                int r = li >> 2;
                int kq = (li & 3) * 4;
                int gk = k0 + kq;
                const float* Ap; int ld;
                if (gk < p.ksplit) { Ap = A0; ld = p.lda0; }
                else { Ap = p.A1; ld = p.lda1; gk -= p.ksplit; }
                float4 v = *(const float4*)(Ap + (long)(bm + r) * ld + gk);
                As[kq + 0][r] = v.x; As[kq + 1][r] = v.y;
                As[kq + 2][r] = v.z; As[kq + 3][r] = v.w;
            }
        } else {
#pragma unroll
            for (int it = 0; it < 2; ++it) {
                int li = tid + it * 256;
                int kr = li >> 5;
                int m4 = (li & 31) * 4;
                float4 v = *(const float4*)(A0 + (long)(k0 + kr) * p.lda0 + bm + m4);
                *(float4*)&As[kr][m4] = v;
            }
        }
        if (TB == 0) {
#pragma unroll
            for (int it = 0; it < 2; ++it) {
                int li = tid + it * 256;
                int kr = li >> 5;
                int n4 = (li & 31) * 4;
                int gk = k0 + kr;
                const float* Bp; int ld;
                if (gk < p.ksplit) { Bp = B0; ld = p.ldb0; }
                else { Bp = p.B1; ld = p.ldb1; gk -= p.ksplit; }
                float4 v = *(const float4*)(Bp + (long)gk * ld + bn + n4);
                *(float4*)&Bs[kr][n4] = v;
            }
        } else {
#pragma unroll
            for (int it = 0; it < 2; ++it) {
                int li = tid + it * 256;
                int r = li >> 2;
                int kq = (li & 3) * 4;
                float4 v = *(const float4*)(B0 + (long)(bn + r) * p.ldb0 + k0 + kq);
                Bs[kq + 0][r] = v.x; Bs[kq + 1][r] = v.y;
                Bs[kq + 2][r] = v.z; Bs[kq + 3][r] = v.w;
            }
        }
        __syncthreads();
#pragma unroll
        for (int kk = 0; kk < 16; ++kk) {
            float4 a0 = *(const float4*)&As[kk][ty * 8];
            float4 a1 = *(const float4*)&As[kk][ty * 8 + 4];
            float4 b0 = *(const float4*)&Bs[kk][tx * 8];
            float4 b1 = *(const float4*)&Bs[kk][tx * 8 + 4];
            float a[8] = {a0.x, a0.y, a0.z, a0.w, a1.x, a1.y, a1.z, a1.w};
            float bb[8] = {b0.x, b0.y, b0.z, b0.w, b1.x, b1.y, b1.z, b1.w};
#pragma unroll
            for (int i = 0; i < 8; i++)
#pragma unroll
                for (int j = 0; j < 8; j++)
                    acc[i][j] = fmaf(a[i], bb[j], acc[i][j]);
        }
        __syncthreads();
    }
    float al = p.aConst;
    if (p.sIdx >= 0) {
        float s = g_scale[p.sIdx + z * p.sStride];
        al *= (p.sPow == 2) ? s * s : s;
    }
#pragma unroll
    for (int i = 0; i < 8; i++) {
        int r = bm + ty * 8 + i;
#pragma unroll
        for (int j = 0; j < 8; j++) {
            int c = bn + tx * 8 + j;
            C[(long)r * p.ldc + c] = al * acc[i][j];
        }
    }
}

// ==================== mma.sync split-bf16 GEMM (forward) ====================
struct TCP {
    const float *A0, *A1, *B0, *B1, *S1, *bias;
    float* C;
    int lda0, lda1, ldb0, ldb1, ldc, ld1;
    int kChunks, kSplitCh;     // chunk = 32 fp32 along K
    int epi;                   // 0 plain | 2 relu+bias | 3 -S1 | 4 S1- | 5 final
    float alpha, c1;
};
// smem: 2 stages; stage = {Ahi,Alo,Bhi,Blo}, each [128][40] bf16 (10240 B)
#define MM_STAGE_B 40960
#define MM_SMEM (2 * MM_STAGE_B)

__device__ __forceinline__ uint32_t smem_u32(const void* p) {
    uint32_t a;
    asm("{ .reg .u64 t; cvta.to.shared.u64 t, %1; cvt.u32.u64 %0, t; }"
        : "=r"(a) : "l"(p));
    return a;
}
__device__ __forceinline__ void ldsm4(uint32_t* r, uint32_t addr) {
    asm volatile("ldmatrix.sync.aligned.m8n8.x4.shared.b16 {%0,%1,%2,%3}, [%4];"
        : "=r"(r[0]), "=r"(r[1]), "=r"(r[2]), "=r"(r[3]) : "r"(addr));
}
__device__ __forceinline__ void mma_bf16(float* d, const uint32_t* a, const uint32_t* b) {
    asm volatile(
        "mma.sync.aligned.m16n8k16.row.col.f32.bf16.bf16.f32 "
        "{%0,%1,%2,%3},{%4,%5,%6,%7},{%8,%9},{%0,%1,%2,%3};"
        : "+f"(d[0]), "+f"(d[1]), "+f"(d[2]), "+f"(d[3])
        : "r"(a[0]), "r"(a[1]), "r"(a[2]), "r"(a[3]), "r"(b[0]), "r"(b[1]));
}
__device__ __forceinline__ void cvt_store16(__nv_bfloat16* Hi, __nv_bfloat16* Lo,
                                            int idx, const float* f) {
    uint32_t h[8], l[8];
#pragma unroll
    for (int i = 0; i < 8; i++) {
        float x = f[2 * i], y = f[2 * i + 1];
        __nv_bfloat162 hb = __floats2bfloat162_rn(x, y);
        float rx = x - __bfloat162float(hb.x);
        float ry = y - __bfloat162float(hb.y);
        __nv_bfloat162 lb = __floats2bfloat162_rn(rx, ry);
        h[i] = *(uint32_t*)&hb; l[i] = *(uint32_t*)&lb;
    }
    *(uint4*)(Hi + idx)     = make_uint4(h[0], h[1], h[2], h[3]);
    *(uint4*)(Hi + idx + 8) = make_uint4(h[4], h[5], h[6], h[7]);
    *(uint4*)(Lo + idx)     = make_uint4(l[0], l[1], l[2], l[3]);
    *(uint4*)(Lo + idx + 8) = make_uint4(l[4], l[5], l[6], l[7]);
}

__global__ void __launch_bounds__(256, 1) mma_gemm(TCP p) {
    extern __shared__ __nv_bfloat16 sm[];
    uint32_t sbase = smem_u32(sm);
    int tid = threadIdx.x, lane = tid & 31, wid = tid >> 5;
    int wm = wid & 3, wn = wid >> 2;       // 4 M-warps x 2 N-warps
    int bm = blockIdx.y * 128, bn = blockIdx.x * 128;

    float acc[2][8][4];
#pragma unroll
    for (int i = 0; i < 2; i++)
#pragma unroll
        for (int j = 0; j < 8; j++)
#pragma unroll
            for (int q = 0; q < 4; q++) acc[i][j][q] = 0.f;

    // loader mapping: thread -> row (0..127), k-half (0/16)
    int lr = tid >> 1, lk = (tid & 1) * 16;
    float fa[16], fb[16];

    auto gload = [&](int c) {
        int kk = (c < p.kSplitCh) ? c * 32 + lk : (c - p.kSplitCh) * 32 + lk;
        const float* Ap = (c < p.kSplitCh) ? p.A0 : p.A1;
        int lda = (c < p.kSplitCh) ? p.lda0 : p.lda1;
        const float* a = Ap + (long)(bm + lr) * lda + kk;
#pragma unroll
        for (int i = 0; i < 4; i++) ((float4*)fa)[i] = *(const float4*)(a + i * 4);
        const float* Bp = (c < p.kSplitCh) ? p.B0 : p.B1;
        int ldb = (c < p.kSplitCh) ? p.ldb0 : p.ldb1;
        const float* bpt = Bp + (long)(bn + lr) * ldb + kk;
#pragma unroll
        for (int i = 0; i < 4; i++) ((float4*)fb)[i] = *(const float4*)(bpt + i * 4);
    };
    auto sstore = [&](int stg) {
        __nv_bfloat16* base = sm + stg * 20480;
        int idx = lr * 40 + lk;
        cvt_store16(base,         base + 5120,  idx, fa);
        cvt_store16(base + 10240, base + 15360, idx, fb);
    };
    auto compute = [&](int stg) {
        uint32_t s0 = sbase + stg * MM_STAGE_B;
        int arow = wm * 32 + (lane & 15);
        int acol = (lane >> 4) << 3;
        int brow = wn * 64 + (lane & 7) + ((lane & 16) >> 1);
        int bcol = lane & 8;
#pragma unroll
        for (int ks = 0; ks < 2; ks++) {
            int kc = ks * 16;
            uint32_t Ah[2][4], Al[2][4];
#pragma unroll
            for (int mt = 0; mt < 2; mt++) {
                uint32_t ad = s0 + ((arow + mt * 16) * 40 + kc + acol) * 2;
                ldsm4(Ah[mt], ad);
                ldsm4(Al[mt], ad + 10240);
            }
            uint32_t Bh[4][4], Bl[4][4];
#pragma unroll
            for (int g = 0; g < 4; g++) {
                uint32_t bd = s0 + 20480 + ((brow + g * 16) * 40 + kc + bcol) * 2;
                ldsm4(Bh[g], bd);
                ldsm4(Bl[g], bd + 10240);
            }
#pragma unroll
            for (int mt = 0; mt < 2; mt++)
#pragma unroll
                for (int nt = 0; nt < 8; nt++) {
                    const uint32_t* bh = &Bh[nt >> 1][(nt & 1) * 2];
                    const uint32_t* bl = &Bl[nt >> 1][(nt & 1) * 2];
                    mma_bf16(acc[mt][nt], Ah[mt], bh);
                    mma_bf16(acc[mt][nt], Ah[mt], bl);
                    mma_bf16(acc[mt][nt], Al[mt], bh);
                }
        }
    };

    gload(0);
    sstore(0);
    __syncthreads();
    for (int c = 0; c < p.kChunks; ++c) {
        if (c + 1 < p.kChunks) gload(c + 1);
        compute(c & 1);
        __syncthreads();
        if (c + 1 < p.kChunks) {
            sstore((c + 1) & 1);
            __syncthreads();
        }
    }

    // epilogue
    float al = p.alpha;
#pragma unroll
    for (int mt = 0; mt < 2; mt++) {
#pragma unroll
        for (int nt = 0; nt < 8; nt++) {
            int r0 = bm + wm * 32 + mt * 16 + (lane >> 2);
            int c0 = bn + wn * 64 + nt * 8 + (lane & 3) * 2;
#pragma unroll
            for (int h = 0; h < 2; h++) {
                int r = r0 + h * 8;
                float v0 = al * acc[mt][nt][h * 2 + 0];
                float v1 = al * acc[mt][nt][h * 2 + 1];
                switch (p.epi) {
                    case 2:
                        v0 = fmaxf(v0 + p.bias[c0], 0.f);
                        v1 = fmaxf(v1 + p.bias[c0 + 1], 0.f);
                        break;
                    case 3:
                        v0 -= p.S1[(long)r * p.ld1 + c0];
                        v1 -= p.S1[(long)r * p.ld1 + c0 + 1];
                        break;
                    case 4:
                        v0 = p.S1[(long)r * p.ld1 + c0] - v0;
                        v1 = p.S1[(long)r * p.ld1 + c0 + 1] - v1;
                        break;
                    case 5:
                        v0 = v0 + p.c1 * p.S1[(long)r * p.ld1 + c0] + p.bias[c0];
                        v1 = v1 + p.c1 * p.S1[(long)r * p.ld1 + c0 + 1] + p.bias[c0 + 1];
                        break;
                    default: break;
                }
                float2 o; o.x = v0; o.y = v1;
                *(float2*)(p.C + (long)r * p.ldc + c0) = o;
            }
        }
    }
}

// ==================== host ====================
static GP mk(const float* A, int lda, const float* B, int ldb, float* C, int ldc,
             int M, int N, int K) {
    GP p; memset(&p, 0, sizeof(p));
    p.A0 = A; p.lda0 = lda; p.B0 = B; p.ldb0 = ldb; p.C = C; p.ldc = ldc;
    p.M = M; p.N = N; p.K = K; p.ksplit = K; p.sIdx = -1; p.aConst = 1.f;
    return p;
}
static void G(int TA, int TB, const GP& p, int batch = 1) {
    dim3 g(p.N / 128, p.M / 128, batch);
    if (TA == 0 && TB == 0) gemm_k<0, 0><<<g, 256>>>(p);
    else if (TA == 0)       gemm_k<0, 1><<<g, 256>>>(p);
    else                    gemm_k<1, 0><<<g, 256>>>(p);
}
static void TCG(const TCP& p, int M, int N) {
    dim3 g(N / 128, M / 128);
    mma_gemm<<<g, 256, MM_SMEM>>>(p);
}
static float* sym(const void* s) {
    void* ptr = nullptr;
    cudaGetSymbolAddress(&ptr, s);
    return (float*)ptr;
}

extern "C" void kernel_launch(void* const* d_in, const int* in_sizes, int n_in,
                              void* d_out, int out_size) {
    const float* x   = (const float*)d_in[0];
    const float* Fq  = (const float*)d_in[1];
    const float* fq  = (const float*)d_in[2];
    const float* by  = (const float*)d_in[3];
    const float* Fr0 = (const float*)d_in[4];
    const float* Frr = (const float*)d_in[5];
    const float* fr  = (const float*)d_in[6];
    const float* b   = (const float*)d_in[7];
    float* out = (float*)d_out;

    cudaFuncSetAttribute(mma_gemm, cudaFuncAttributeMaxDynamicSharedMemorySize, MM_SMEM);

    float* Aq    = sym(g_Aq);
    float* Wq    = sym(g_Wq);
    float* ImAq  = sym(g_ImAq);
    float* Arr   = sym(g_Ar);
    float* Wr    = sym(g_Wr);
    float* ImAr  = sym(g_ImAr);
    float* DinvQ = sym(g_DinvQ);
    float* CpanQ = sym(g_CpanQ);
    float* TQ    = sym(g_TQ);
    float* DinvR = sym(g_DinvR);
    float* CpanR = sym(g_CpanR);
    float* TR    = sym(g_TR);
    float* Pm    = sym(g_P);
    float* Gsm   = sym(g_Gs);
    float* PT    = sym(g_PT);
    float* GT    = sym(g_GT);
    float* Qm    = sym(g_Qm);
    float* QmT   = sym(g_QmT);
    float* xh    = sym(g_xh);
    float* act   = sym(g_act);
    float* h0    = sym(g_h0);
    float* h1    = sym(g_h1);
    float* yh    = sym(g_yh);

    // ---- scales ----
    red_in<<<dim3(64, 9), 256>>>(Fq, Fr0, Frr);
    red_in_fin<<<1, 32>>>(fq, fr);

    // ---- A matrices ----
    { GP p = mk(Fq + 1048576, 1024, Fq + 1048576, 1024, Aq, 1024, 1024, 1024, 3072);
      p.sIdx = 0; p.sStride = 0; p.sPow = 2; G(1, 0, p); }
    { GP p = mk(Frr + 512, 1024, Frr + 512, 1024, Arr, 512, 512, 512, 512);
      p.sA = 524288; p.sB = 524288; p.sC = 262144;
      p.sIdx = 2; p.sStride = 1; p.sPow = 2; G(0, 1, p, 7); }
    prepQ<<<4096, 256>>>(Fq);
    prepR<<<8192, 256>>>(Fr0, Frr);

    // ---- inversions (blocked GJ) ----
    for (int s = 0; s < 16; s++) {
        gj_diag<<<1, 256>>>(Wq, 1024, s, DinvQ, CpanQ, 0, 0, 0);
        gj_row<<<dim3(16, 1), 256>>>(Wq, 1024, s, DinvQ, TQ, 0, 0, 0);
        gj_upd<<<dim3(16, 16, 1), 256>>>(Wq, 1024, s, CpanQ, TQ, 0, 0, 0);
    }
    for (int s = 0; s < 8; s++) {
        gj_diag<<<8, 256>>>(Wr, 512, s, DinvR, CpanR, 262144, 4096, 32768);
        gj_row<<<dim3(8, 8), 256>>>(Wr, 512, s, DinvR, TR, 262144, 4096, 32768);
        gj_upd<<<dim3(8, 8, 8), 256>>>(Wr, 512, s, CpanR, TR, 262144, 32768, 32768);
    }

    // ---- assemble Q / P / Gs ----
    { GP p = mk(Wq, 1024, ImAq, 1024, Qm, 1024, 1024, 1024, 1024); G(0, 0, p); }
    { GP p = mk(Fq + 1048576, 1024, Wq, 1024, Qm + 1048576, 1024, 3072, 1024, 1024);
      p.sIdx = 0; p.sStride = 0; p.sPow = 1; p.aConst = -2.f; G(0, 0, p); }
    { GP p = mk(Wr, 512, ImAr, 512, Pm, 512, 512, 512, 512);
      p.sA = p.sB = p.sC = 262144; G(0, 0, p, 8); }
    { GP p = mk(Frr + 512, 1024, Wr + 262144, 512, Gsm, 512, 512, 512, 512);
      p.sA = 524288; p.sB = 262144; p.sC = 262144;
      p.sIdx = 2; p.sStride = 1; p.sPow = 1; p.aConst = -2.f; G(1, 0, p, 7); }

    // ---- transposes for mma B-operands ----
    tr_k<<<dim3(32, 128), 256>>>(Qm, QmT, 4096, 1024, 0, 0);
    tr_k<<<dim3(16, 16, 8), 256>>>(Pm, PT, 512, 512, 262144, 262144);
    tr_k<<<dim3(16, 16, 7), 256>>>(Gsm, GT, 512, 512, 262144, 262144);

    // ---- forward pass on tensor cores (mma.sync) ----
    // xh = SQG * x @ Q^T   (B = Qm, N-major)
    { TCP t; memset(&t, 0, sizeof(t));
      t.A0 = x; t.lda0 = 1024; t.B0 = Qm; t.ldb0 = 1024;
      t.C = xh; t.ldc = 4096; t.kChunks = 32; t.kSplitCh = 32;
      t.epi = 0; t.alpha = SQG; TCG(t, 8192, 4096); }

    // layer 0: act = relu(SQ2 * xk @ P0^T + b0)   (B = Pm)
    { TCP t; memset(&t, 0, sizeof(t));
      t.A0 = xh; t.lda0 = 4096; t.B0 = Pm; t.ldb0 = 512;
      t.C = act; t.ldc = 512; t.kChunks = 16; t.kSplitCh = 16;
      t.epi = 2; t.alpha = SQ2; t.bias = b; TCG(t, 8192, 512); }
    // h0 = SQ2 * act @ P0 - xk   (B = PT)
    { TCP t; memset(&t, 0, sizeof(t));
      t.A0 = act; t.lda0 = 512; t.B0 = PT; t.ldb0 = 512;
      t.C = h0; t.ldc = 512; t.kChunks = 16; t.kSplitCh = 16;
      t.epi = 3; t.alpha = SQ2; t.S1 = xh; t.ld1 = 4096; TCG(t, 8192, 512); }

    float* hb[2] = {h0, h1};
    for (int k = 1; k < 8; k++) {
        float* hp = hb[(k + 1) & 1];
        float* hn = hb[k & 1];
        const float* Pk  = Pm + (long)k * 262144;
        const float* PTk = PT + (long)k * 262144;
        const float* Gk  = Gsm + (long)(k - 1) * 262144;
        const float* GTk = GT + (long)(k - 1) * 262144;
        // pre = relu(SQ2*(xk @ P' + hp @ G') + bk)  (B = PTk | GTk)
        { TCP t; memset(&t, 0, sizeof(t));
          t.A0 = xh + k * 512; t.lda0 = 4096; t.A1 = hp; t.lda1 = 512;
          t.B0 = PTk; t.ldb0 = 512; t.B1 = GTk; t.ldb1 = 512;
          t.C = act; t.ldc = 512; t.kChunks = 32; t.kSplitCh = 16;
          t.epi = 2; t.alpha = SQ2; t.bias = b + k * 512; TCG(t, 8192, 512); }
        // h_new = SQ2 * act @ P'^T... (B = Pk)
        { TCP t; memset(&t, 0, sizeof(t));
          t.A0 = act; t.lda0 = 512; t.B0 = Pk; t.ldb0 = 512;
          t.C = (k == 7 ? yh + 3584 : hn); t.ldc = (k == 7 ? 4096 : 512);
          t.kChunks = 16; t.kSplitCh = 16;
          t.epi = 3; t.alpha = SQ2; t.S1 = xh + k * 512; t.ld1 = 4096;
          TCG(t, 8192, 512); }
        // yh[k-1] = hp - SQ2 * act @ G'  (B = Gk)
        { TCP t; memset(&t, 0, sizeof(t));
          t.A0 = act; t.lda0 = 512; t.B0 = Gk; t.ldb0 = 512;
          t.C = yh + (k - 1) * 512; t.ldc = 4096;
          t.kChunks = 16; t.kSplitCh = 16;
          t.epi = 4; t.alpha = SQ2; t.S1 = hp; t.ld1 = 512;
          TCG(t, 8192, 512); }
    }

    // out = 0.5*SQG * yh @ Q + 5.05 * x + by   (B = QmT)
    { TCP t; memset(&t, 0, sizeof(t));
      t.A0 = yh; t.lda0 = 4096; t.B0 = QmT; t.ldb0 = 4096;
      t.C = out; t.ldc = 1024; t.kChunks = 128; t.kSplitCh = 128;
      t.epi = 5; t.alpha = 0.5f * SQG; t.c1 = 0.5f * (0.1f + 10.0f);
      t.S1 = x; t.ld1 = 1024; t.bias = by; TCG(t, 8192, 1024); }
}

// round 6
// speedup vs baseline: 2.7724x; 1.2639x over previous
#include <cuda_runtime.h>
#include <cuda_bf16.h>
#include <math.h>
#include <stdint.h>

#define SQG 3.1464265445104548f   /* sqrt(NU-MU)=sqrt(9.9) */
#define SQ2 1.4142135623730951f

// ==================== device scratch ====================
__device__ float g_scale[9];
__device__ float g_part[9 * 64];
__device__ float g_Aq[1024 * 1024];
__device__ float g_Wq[1024 * 1024];
__device__ float g_WqT[1024 * 1024];
__device__ float g_ImAqT[1024 * 1024];
__device__ float g_VT[1024 * 3072];
__device__ float g_Ar[7 * 512 * 512];
__device__ float g_Wr[8 * 512 * 512];
__device__ float g_WrT[8 * 512 * 512];
__device__ float g_ImArT[8 * 512 * 512];
__device__ float g_B2T[7 * 512 * 512];
__device__ float g_DinvQ[64 * 64];
__device__ float g_CpanQ[1024 * 64];
__device__ float g_TQ[64 * 1024];
__device__ float g_DinvR[8 * 64 * 64];
__device__ float g_CpanR[8 * 512 * 64];
__device__ float g_TR[8 * 64 * 512];
__device__ float g_P[8 * 512 * 512];
__device__ float g_Gs[7 * 512 * 512];
__device__ float g_PT[8 * 512 * 512];
__device__ float g_GT[7 * 512 * 512];
__device__ float g_Qm[4096 * 1024];
__device__ float g_QmT[1024 * 4096];
__device__ float g_xh[8192u * 4096u];
__device__ float g_act[8192u * 512u];
__device__ float g_h0[8192u * 512u];
__device__ float g_h1[8192u * 512u];
__device__ float g_yh[8192u * 4096u];

// ==================== reductions ====================
__global__ void red_in(const float* Fq, const float* Fr0, const float* Frr) {
    __shared__ float sh[256];
    int z = blockIdx.y;
    const float* p; long n;
    if (z == 0)      { p = Fq;  n = 4096L * 1024; }
    else if (z == 1) { p = Fr0; n = 512L * 512; }
    else             { p = Frr + (long)(z - 2) * 512 * 1024; n = 512L * 1024; }
    float s = 0.f;
    for (long i = (long)blockIdx.x * 256 + threadIdx.x; i < n; i += 64L * 256) {
        float v = p[i]; s += v * v;
    }
    sh[threadIdx.x] = s; __syncthreads();
    for (int o = 128; o > 0; o >>= 1) {
        if (threadIdx.x < o) sh[threadIdx.x] += sh[threadIdx.x + o];
        __syncthreads();
    }
    if (threadIdx.x == 0) g_part[z * 64 + blockIdx.x] = sh[0];
}
__global__ void red_in_fin(const float* fq, const float* fr) {
    int t = threadIdx.x;
    if (t < 9) {
        float s = 0.f;
        for (int i = 0; i < 64; i++) s += g_part[t * 64 + i];
        float f = (t == 0) ? fq[0] : fr[t - 1];
        g_scale[t] = f / (sqrtf(s) + 1e-5f);
    }
}

// ==================== elementwise prep (writes W = I+A and (I-A)^T) ====================
__global__ void prepQ(const float* Fq) {
    int e = blockIdx.x * 256 + threadIdx.x;
    int i = e >> 10, j = e & 1023;
    float s = g_scale[0];
    float a = g_Aq[e] + s * (Fq[i * 1024 + j] - Fq[j * 1024 + i]);
    float d = (i == j) ? 1.f : 0.f;
    g_Wq[e] = d + a;
    g_ImAqT[j * 1024 + i] = d - a;
}
__global__ void prepR(const float* Fr0, const float* Frr) {
    int e = blockIdx.x * 256 + threadIdx.x;
    int z = e >> 18; int r = e & 262143;
    int i = r >> 9, j = r & 511;
    float a;
    if (z == 0) {
        float s = g_scale[1];
        a = s * (Fr0[i * 512 + j] - Fr0[j * 512 + i]);
    } else {
        float s = g_scale[1 + z];
        const float* B = Frr + (long)(z - 1) * 524288;
        a = g_Ar[(long)(z - 1) * 262144 + r] + s * (B[j * 1024 + i] - B[i * 1024 + j]);
    }
    float d = (i == j) ? 1.f : 0.f;
    g_Wr[e] = d + a;
    g_ImArT[z * 262144 + j * 512 + i] = d - a;
}

// ==================== transpose (dst[c][r] = src[r][c]) ====================
__global__ void tr_k(const float* src, float* dst, int ldS, int ldD, long sS, long sD) {
    int z = blockIdx.z;
    src += (long)z * sS; dst += (long)z * sD;
    __shared__ float t[32][33];
    int r0 = blockIdx.y * 32, c0 = blockIdx.x * 32;
    int tx = threadIdx.x & 31, ty = threadIdx.x >> 5;
    for (int i = ty; i < 32; i += 8) t[i][tx] = src[(long)(r0 + i) * ldS + c0 + tx];
    __syncthreads();
    for (int i = ty; i < 32; i += 8) dst[(long)(c0 + i) * ldD + r0 + tx] = t[tx][i];
}

// ==================== blocked in-place Gauss-Jordan (block 64) ====================
__device__ void gj_diag_body(float* W, int n, int s, float* Dinv, float* Cpan) {
    int t = threadIdx.x;
    for (int e = t; e < n * 64; e += 256) {
        int i = e >> 6, c = e & 63;
        Cpan[e] = W[(long)i * n + s * 64 + c];
    }
    __shared__ float sh[64][65];
    for (int e = t; e < 4096; e += 256) {
        int i = e >> 6, j = e & 63;
        sh[i][j] = W[(long)(s * 64 + i) * n + s * 64 + j];
    }
    __syncthreads();
    int jc = t & 63, rb = (t >> 6) * 16;
    for (int p = 0; p < 64; p++) {
        float d = 1.0f / sh[p][p];
        float c[16];
#pragma unroll
        for (int r = 0; r < 16; r++) c[r] = sh[rb + r][p];
        float pv = sh[p][jc];
        __syncthreads();
        float npv = (jc == p) ? d : pv * d;
#pragma unroll
        for (int r = 0; r < 16; r++) {
            int i = rb + r;
            if (i == p)       sh[i][jc] = npv;
            else if (jc == p) sh[i][jc] = -c[r] * d;
            else              sh[i][jc] = sh[i][jc] - c[r] * npv;
        }
        __syncthreads();
    }
    for (int e = t; e < 4096; e += 256) Dinv[e] = sh[e >> 6][e & 63];
}
__device__ void gj_row_body(const float* W, int n, int s, int jb,
                            const float* Dinv, float* T) {
    int t = threadIdx.x;
    if (jb == s) {
        for (int e = t; e < 4096; e += 256)
            T[(long)(e >> 6) * n + s * 64 + (e & 63)] = Dinv[e];
        return;
    }
    __shared__ float shD[64][65], shW[64][65];
    for (int e = t; e < 4096; e += 256) {
        int i = e >> 6, j = e & 63;
        shD[i][j] = Dinv[e];
        shW[i][j] = W[(long)(s * 64 + i) * n + jb * 64 + j];
    }
    __syncthreads();
    int jc = t & 63, rb = (t >> 6) * 16;
    float acc[16];
#pragma unroll
    for (int r = 0; r < 16; r++) acc[r] = 0.f;
    for (int k = 0; k < 64; k++) {
        float bv = shW[k][jc];
#pragma unroll
        for (int r = 0; r < 16; r++) acc[r] = fmaf(shD[rb + r][k], bv, acc[r]);
    }
#pragma unroll
    for (int r = 0; r < 16; r++)
        T[(long)(rb + r) * n + jb * 64 + jc] = acc[r];
}
__device__ void gj_upd_body(float* W, int n, int s, int jb, int ib,
                            const float* Cpan, const float* T) {
    int t = threadIdx.x;
    if (ib == s) {
        for (int e = t; e < 4096; e += 256) {
            int i = e >> 6, j = e & 63;
            W[(long)(s * 64 + i) * n + jb * 64 + j] = T[(long)i * n + jb * 64 + j];
        }
        return;
    }
    __shared__ float shC[64][65], shT[64][65];
    for (int e = t; e < 4096; e += 256) {
        int i = e >> 6, j = e & 63;
        shC[i][j] = Cpan[(long)(ib * 64 + i) * 64 + j];
        shT[i][j] = T[(long)i * n + jb * 64 + j];
    }
    __syncthreads();
    int jc = t & 63, rb = (t >> 6) * 16;
    float acc[16];
#pragma unroll
    for (int r = 0; r < 16; r++) acc[r] = 0.f;
    for (int k = 0; k < 64; k++) {
        float tv = shT[k][jc];
#pragma unroll
        for (int r = 0; r < 16; r++) acc[r] = fmaf(shC[rb + r][k], tv, acc[r]);
    }
#pragma unroll
    for (int r = 0; r < 16; r++) {
        long idx = (long)(ib * 64 + rb + r) * n + jb * 64 + jc;
        float oldv = (jb == s) ? 0.f : W[idx];
        W[idx] = oldv - acc[r];
    }
}
// combined: z=0 -> Q (n=1024, 16 steps), z in 1..8 -> R[z-1] (n=512, 8 steps)
__global__ void cgj_diag(float* WQ, float* WR, int s,
                         float* DQ, float* DR, float* CQ, float* CR) {
    int z = blockIdx.x;
    if (z == 0) { gj_diag_body(WQ, 1024, s, DQ, CQ); return; }
    if (s >= 8) return;
    gj_diag_body(WR + (long)(z - 1) * 262144, 512, s,
                 DR + (long)(z - 1) * 4096, CR + (long)(z - 1) * 32768);
}
__global__ void cgj_row(const float* WQ, const float* WR, int s,
                        const float* DQ, const float* DR, float* TQp, float* TRp) {
    int z = blockIdx.y, jb = blockIdx.x;
    if (z == 0) { gj_row_body(WQ, 1024, s, jb, DQ, TQp); return; }
    if (s >= 8 || jb >= 8) return;
    gj_row_body(WR + (long)(z - 1) * 262144, 512, s, jb,
                DR + (long)(z - 1) * 4096, TRp + (long)(z - 1) * 32768);
}
__global__ void cgj_upd(float* WQ, float* WR, int s,
                        const float* CQ, const float* CR,
                        const float* TQp, const float* TRp) {
    int z = blockIdx.z, jb = blockIdx.x, ib = blockIdx.y;
    if (z == 0) { gj_upd_body(WQ, 1024, s, jb, ib, CQ, TQp); return; }
    if (s >= 8 || jb >= 8 || ib >= 8) return;
    gj_upd_body(WR + (long)(z - 1) * 262144, 512, s, jb, ib,
                CR + (long)(z - 1) * 32768, TRp + (long)(z - 1) * 32768);
}

// ==================== mma.sync split-bf16 GEMM ====================
struct TCP {
    const float *A0, *A1, *B0, *B1, *S1, *bias;
    float* C;
    int lda0, lda1, ldb0, ldb1, ldc, ld1;
    long sA, sB, sC;
    int kChunks, kSplitCh;     // chunk = 32 fp32 along K
    int epi;                   // 0 plain | 2 relu+bias | 3 -S1 | 4 S1- | 5 final
    int sIdx, sStride, sPow;
    float alpha, c1;
};
// smem: 2 stages; stage = {Ahi,Alo,Bhi,Blo}, each [128][40] bf16 (10240 B)
#define MM_STAGE_B 40960
#define MM_SMEM (2 * MM_STAGE_B)

__device__ __forceinline__ uint32_t smem_u32(const void* p) {
    uint32_t a;
    asm("{ .reg .u64 t; cvta.to.shared.u64 t, %1; cvt.u32.u64 %0, t; }"
        : "=r"(a) : "l"(p));
    return a;
}
__device__ __forceinline__ void ldsm4(uint32_t* r, uint32_t addr) {
    asm volatile("ldmatrix.sync.aligned.m8n8.x4.shared.b16 {%0,%1,%2,%3}, [%4];"
        : "=r"(r[0]), "=r"(r[1]), "=r"(r[2]), "=r"(r[3]) : "r"(addr));
}
__device__ __forceinline__ void mma_bf16(float* d, const uint32_t* a, const uint32_t* b) {
    asm volatile(
        "mma.sync.aligned.m16n8k16.row.col.f32.bf16.bf16.f32 "
        "{%0,%1,%2,%3},{%4,%5,%6,%7},{%8,%9},{%0,%1,%2,%3};"
        : "+f"(d[0]), "+f"(d[1]), "+f"(d[2]), "+f"(d[3])
        : "r"(a[0]), "r"(a[1]), "r"(a[2]), "r"(a[3]), "r"(b[0]), "r"(b[1]));
}
__device__ __forceinline__ void cvt_store16(__nv_bfloat16* Hi, __nv_bfloat16* Lo,
                                            int idx, const float* f) {
    uint32_t h[8], l[8];
#pragma unroll
    for (int i = 0; i < 8; i++) {
        float x = f[2 * i], y = f[2 * i + 1];
        __nv_bfloat162 hb = __floats2bfloat162_rn(x, y);
        float rx = x - __bfloat162float(hb.x);
        float ry = y - __bfloat162float(hb.y);
        __nv_bfloat162 lb = __floats2bfloat162_rn(rx, ry);
        h[i] = *(uint32_t*)&hb; l[i] = *(uint32_t*)&lb;
    }
    *(uint4*)(Hi + idx)     = make_uint4(h[0], h[1], h[2], h[3]);
    *(uint4*)(Hi + idx + 8) = make_uint4(h[4], h[5], h[6], h[7]);
    *(uint4*)(Lo + idx)     = make_uint4(l[0], l[1], l[2], l[3]);
    *(uint4*)(Lo + idx + 8) = make_uint4(l[4], l[5], l[6], l[7]);
}

__global__ void __launch_bounds__(256, 1) mma_gemm(TCP p) {
    extern __shared__ __nv_bfloat16 sm[];
    uint32_t sbase = smem_u32(sm);
    int tid = threadIdx.x, lane = tid & 31, wid = tid >> 5;
    int wm = wid & 3, wn = wid >> 2;       // 4 M-warps x 2 N-warps
    int bm = blockIdx.y * 128, bn = blockIdx.x * 128;
    int z = blockIdx.z;
    const float* A0z = p.A0 + (long)z * p.sA;
    const float* B0z = p.B0 + (long)z * p.sB;
    float* Cz = p.C + (long)z * p.sC;

    float acc[2][8][4];
#pragma unroll
    for (int i = 0; i < 2; i++)
#pragma unroll
        for (int j = 0; j < 8; j++)
#pragma unroll
            for (int q = 0; q < 4; q++) acc[i][j][q] = 0.f;

    int lr = tid >> 1, lk = (tid & 1) * 16;
    float fa[16], fb[16];

    auto gload = [&](int c) {
        int kk; const float* Ap; int lda;
        if (c < p.kSplitCh) { Ap = A0z; lda = p.lda0; kk = c * 32 + lk; }
        else { Ap = p.A1; lda = p.lda1; kk = (c - p.kSplitCh) * 32 + lk; }
        const float* a = Ap + (long)(bm + lr) * lda + kk;
#pragma unroll
        for (int i = 0; i < 4; i++) ((float4*)fa)[i] = *(const float4*)(a + i * 4);
        const float* Bp; int ldb;
        if (c < p.kSplitCh) { Bp = B0z; ldb = p.ldb0; kk = c * 32 + lk; }
        else { Bp = p.B1; ldb = p.ldb1; kk = (c - p.kSplitCh) * 32 + lk; }
        const float* bpt = Bp + (long)(bn + lr) * ldb + kk;
#pragma unroll
        for (int i = 0; i < 4; i++) ((float4*)fb)[i] = *(const float4*)(bpt + i * 4);
    };
    auto sstore = [&](int stg) {
        __nv_bfloat16* base = sm + stg * 20480;
        int idx = lr * 40 + lk;
        cvt_store16(base,         base + 5120,  idx, fa);
        cvt_store16(base + 10240, base + 15360, idx, fb);
    };
    auto compute = [&](int stg) {
        uint32_t s0 = sbase + stg * MM_STAGE_B;
        int arow = wm * 32 + (lane & 15);
        int acol = (lane >> 4) << 3;
        int brow = wn * 64 + (lane & 7) + ((lane & 16) >> 1);
        int bcol = lane & 8;
#pragma unroll
        for (int ks = 0; ks < 2; ks++) {
            int kc = ks * 16;
            uint32_t Ah[2][4], Al[2][4];
#pragma unroll
            for (int mt = 0; mt < 2; mt++) {
                uint32_t ad = s0 + ((arow + mt * 16) * 40 + kc + acol) * 2;
                ldsm4(Ah[mt], ad);
                ldsm4(Al[mt], ad + 10240);
            }
            uint32_t Bh[4][4], Bl[4][4];
#pragma unroll
            for (int g = 0; g < 4; g++) {
                uint32_t bd = s0 + 20480 + ((brow + g * 16) * 40 + kc + bcol) * 2;
                ldsm4(Bh[g], bd);
                ldsm4(Bl[g], bd + 10240);
            }
#pragma unroll
            for (int mt = 0; mt < 2; mt++)
#pragma unroll
                for (int nt = 0; nt < 8; nt++) {
                    const uint32_t* bh = &Bh[nt >> 1][(nt & 1) * 2];
                    const uint32_t* bl = &Bl[nt >> 1][(nt & 1) * 2];
                    mma_bf16(acc[mt][nt], Ah[mt], bh);
                    mma_bf16(acc[mt][nt], Ah[mt], bl);
                    mma_bf16(acc[mt][nt], Al[mt], bh);
                }
        }
    };

    // pipeline: one barrier per chunk; store-next / load-next+1 before compute
    gload(0);
    sstore(0);
    __syncthreads();
    if (p.kChunks > 1) gload(1);
    for (int c = 0; c < p.kChunks; ++c) {
        if (c + 1 < p.kChunks) sstore((c + 1) & 1);
        if (c + 2 < p.kChunks) gload(c + 2);
        compute(c & 1);
        __syncthreads();
    }

    // epilogue
    float al = p.alpha;
    if (p.sIdx >= 0) {
        float s = g_scale[p.sIdx + z * p.sStride];
        al *= (p.sPow == 2) ? s * s : s;
    }
#pragma unroll
    for (int mt = 0; mt < 2; mt++) {
#pragma unroll
        for (int nt = 0; nt < 8; nt++) {
            int r0 = bm + wm * 32 + mt * 16 + (lane >> 2);
            int c0 = bn + wn * 64 + nt * 8 + (lane & 3) * 2;
#pragma unroll
            for (int h = 0; h < 2; h++) {
                int r = r0 + h * 8;
                float v0 = al * acc[mt][nt][h * 2 + 0];
                float v1 = al * acc[mt][nt][h * 2 + 1];
                switch (p.epi) {
                    case 2:
                        v0 = fmaxf(v0 + p.bias[c0], 0.f);
                        v1 = fmaxf(v1 + p.bias[c0 + 1], 0.f);
                        break;
                    case 3:
                        v0 -= p.S1[(long)r * p.ld1 + c0];
                        v1 -= p.S1[(long)r * p.ld1 + c0 + 1];
                        break;
                    case 4:
                        v0 = p.S1[(long)r * p.ld1 + c0] - v0;
                        v1 = p.S1[(long)r * p.ld1 + c0 + 1] - v1;
                        break;
                    case 5:
                        v0 = v0 + p.c1 * p.S1[(long)r * p.ld1 + c0] + p.bias[c0];
                        v1 = v1 + p.c1 * p.S1[(long)r * p.ld1 + c0 + 1] + p.bias[c0 + 1];
                        break;
                    default: break;
                }
                float2 o; o.x = v0; o.y = v1;
                *(float2*)(Cz + (long)r * p.ldc + c0) = o;
            }
        }
    }
}

// ==================== host ====================
static TCP mkT() {
    TCP t; memset(&t, 0, sizeof(t));
    t.sIdx = -1; t.alpha = 1.f;
    return t;
}
static void TCG(const TCP& p, int M, int N, int batch = 1) {
    dim3 g(N / 128, M / 128, batch);
    mma_gemm<<<g, 256, MM_SMEM>>>(p);
}
static float* sym(const void* s) {
    void* ptr = nullptr;
    cudaGetSymbolAddress(&ptr, s);
    return (float*)ptr;
}

extern "C" void kernel_launch(void* const* d_in, const int* in_sizes, int n_in,
                              void* d_out, int out_size) {
    const float* x   = (const float*)d_in[0];
    const float* Fq  = (const float*)d_in[1];
    const float* fq  = (const float*)d_in[2];
    const float* by  = (const float*)d_in[3];
    const float* Fr0 = (const float*)d_in[4];
    const float* Frr = (const float*)d_in[5];
    const float* fr  = (const float*)d_in[6];
    const float* b   = (const float*)d_in[7];
    float* out = (float*)d_out;

    cudaFuncSetAttribute(mma_gemm, cudaFuncAttributeMaxDynamicSharedMemorySize, MM_SMEM);

    float* Aq     = sym(g_Aq);
    float* Wq     = sym(g_Wq);
    float* WqT    = sym(g_WqT);
    float* ImAqT  = sym(g_ImAqT);
    float* VT     = sym(g_VT);
    float* Arr    = sym(g_Ar);
    float* Wr     = sym(g_Wr);
    float* WrT    = sym(g_WrT);
    float* ImArT  = sym(g_ImArT);
    float* B2T    = sym(g_B2T);
    float* DinvQ  = sym(g_DinvQ);
    float* CpanQ  = sym(g_CpanQ);
    float* TQ     = sym(g_TQ);
    float* DinvR  = sym(g_DinvR);
    float* CpanR  = sym(g_CpanR);
    float* TR     = sym(g_TR);
    float* Pm     = sym(g_P);
    float* Gsm    = sym(g_Gs);
    float* PT     = sym(g_PT);
    float* GT     = sym(g_GT);
    float* Qm     = sym(g_Qm);
    float* QmT    = sym(g_QmT);
    float* xh     = sym(g_xh);
    float* act    = sym(g_act);
    float* h0     = sym(g_h0);
    float* h1     = sym(g_h1);
    float* yh     = sym(g_yh);

    // ---- scales ----
    red_in<<<dim3(64, 9), 256>>>(Fq, Fr0, Frr);
    red_in_fin<<<1, 32>>>(fq, fr);

    // ---- input transposes ----
    // V (3072x1024, part of Fq) -> VT (1024x3072)
    tr_k<<<dim3(32, 96), 256>>>(Fq + 1048576, VT, 1024, 3072, 0, 0);
    // B2_z (512x512 slices of Frr, ld 1024) -> B2T (512x512)
    tr_k<<<dim3(16, 16, 7), 256>>>(Frr + 512, B2T, 1024, 512, 524288, 262144);

    // ---- A matrices via mma ----
    // Aq = s0^2 * V^T V :  A = VT (M=1024,K=3072), B = VT (N x K)
    { TCP t = mkT();
      t.A0 = VT; t.lda0 = 3072; t.B0 = VT; t.ldb0 = 3072;
      t.C = Aq; t.ldc = 1024; t.kChunks = 96; t.kSplitCh = 96;
      t.sIdx = 0; t.sStride = 0; t.sPow = 2; TCG(t, 1024, 1024); }
    // Ar_z = s_z^2 * B2_z B2_z^T : A = B2 (rows, ld 1024), B = B2 (N x K)
    { TCP t = mkT();
      t.A0 = Frr + 512; t.lda0 = 1024; t.sA = 524288;
      t.B0 = Frr + 512; t.ldb0 = 1024; t.sB = 524288;
      t.C = Arr; t.ldc = 512; t.sC = 262144; t.kChunks = 16; t.kSplitCh = 16;
      t.sIdx = 2; t.sStride = 1; t.sPow = 2; TCG(t, 512, 512, 7); }

    prepQ<<<4096, 256>>>(Fq);
    prepR<<<8192, 256>>>(Fr0, Frr);

    // ---- inversions (combined blocked GJ: z=0 Q 16 steps, z>=1 R 8 steps) ----
    for (int s = 0; s < 16; s++) {
        cgj_diag<<<9, 256>>>(Wq, Wr, s, DinvQ, DinvR, CpanQ, CpanR);
        cgj_row<<<dim3(16, 9), 256>>>(Wq, Wr, s, DinvQ, DinvR, TQ, TR);
        cgj_upd<<<dim3(16, 16, 9), 256>>>(Wq, Wr, s, CpanQ, CpanR, TQ, TR);
    }

    // ---- transposes of inverses ----
    tr_k<<<dim3(32, 32), 256>>>(Wq, WqT, 1024, 1024, 0, 0);
    tr_k<<<dim3(16, 16, 8), 256>>>(Wr, WrT, 512, 512, 262144, 262144);

    // ---- assemble Q / P / Gs via mma ----
    // Qm top = Winv @ (I-A) :  B = ImAqT (N x K)
    { TCP t = mkT();
      t.A0 = Wq; t.lda0 = 1024; t.B0 = ImAqT; t.ldb0 = 1024;
      t.C = Qm; t.ldc = 1024; t.kChunks = 32; t.kSplitCh = 32;
      TCG(t, 1024, 1024); }
    // Qm bottom = -2 s0 * V @ Winv :  B = WqT
    { TCP t = mkT();
      t.A0 = Fq + 1048576; t.lda0 = 1024; t.B0 = WqT; t.ldb0 = 1024;
      t.C = Qm + 1048576; t.ldc = 1024; t.kChunks = 32; t.kSplitCh = 32;
      t.sIdx = 0; t.sStride = 0; t.sPow = 1; t.alpha = -2.f; TCG(t, 3072, 1024); }
    // P_z = Winv_z @ (I-A_z) :  B = ImArT_z
    { TCP t = mkT();
      t.A0 = Wr; t.lda0 = 512; t.sA = 262144;
      t.B0 = ImArT; t.ldb0 = 512; t.sB = 262144;
      t.C = Pm; t.ldc = 512; t.sC = 262144; t.kChunks = 16; t.kSplitCh = 16;
      TCG(t, 512, 512, 8); }
    // Gs_z = -2 s_{2+z} * B2_z^T @ Winv_{z+1} :  A = B2T_z, B = WrT_{z+1}
    { TCP t = mkT();
      t.A0 = B2T; t.lda0 = 512; t.sA = 262144;
      t.B0 = WrT + 262144; t.ldb0 = 512; t.sB = 262144;
      t.C = Gsm; t.ldc = 512; t.sC = 262144; t.kChunks = 16; t.kSplitCh = 16;
      t.sIdx = 2; t.sStride = 1; t.sPow = 1; t.alpha = -2.f; TCG(t, 512, 512, 7); }

    // ---- transposes for forward B-operands ----
    tr_k<<<dim3(32, 128), 256>>>(Qm, QmT, 1024, 4096, 0, 0);
    tr_k<<<dim3(16, 16, 8), 256>>>(Pm, PT, 512, 512, 262144, 262144);
    tr_k<<<dim3(16, 16, 7), 256>>>(Gsm, GT, 512, 512, 262144, 262144);

    // ---- forward pass ----
    // xh = SQG * x @ Q^T   (B = Qm, N-major)
    { TCP t = mkT();
      t.A0 = x; t.lda0 = 1024; t.B0 = Qm; t.ldb0 = 1024;
      t.C = xh; t.ldc = 4096; t.kChunks = 32; t.kSplitCh = 32;
      t.epi = 0; t.alpha = SQG; TCG(t, 8192, 4096); }

    // layer 0: act = relu(SQ2 * xk @ P0^T + b0)   (B = Pm)
    { TCP t = mkT();
      t.A0 = xh; t.lda0 = 4096; t.B0 = Pm; t.ldb0 = 512;
      t.C = act; t.ldc = 512; t.kChunks = 16; t.kSplitCh = 16;
      t.epi = 2; t.alpha = SQ2; t.bias = b; TCG(t, 8192, 512); }
    // h0 = SQ2 * act @ P0 - xk   (B = PT)
    { TCP t = mkT();
      t.A0 = act; t.lda0 = 512; t.B0 = PT; t.ldb0 = 512;
      t.C = h0; t.ldc = 512; t.kChunks = 16; t.kSplitCh = 16;
      t.epi = 3; t.alpha = SQ2; t.S1 = xh; t.ld1 = 4096; TCG(t, 8192, 512); }

    float* hb[2] = {h0, h1};
    for (int k = 1; k < 8; k++) {
        float* hp = hb[(k + 1) & 1];
        float* hn = hb[k & 1];
        const float* Pk  = Pm + (long)k * 262144;
        const float* PTk = PT + (long)k * 262144;
        const float* Gk  = Gsm + (long)(k - 1) * 262144;
        const float* GTk = GT + (long)(k - 1) * 262144;
        // pre = relu(SQ2*(xk @ P' + hp @ G') + bk)  (B = PTk | GTk)
        { TCP t = mkT();
          t.A0 = xh + k * 512; t.lda0 = 4096; t.A1 = hp; t.lda1 = 512;
          t.B0 = PTk; t.ldb0 = 512; t.B1 = GTk; t.ldb1 = 512;
          t.C = act; t.ldc = 512; t.kChunks = 32; t.kSplitCh = 16;
          t.epi = 2; t.alpha = SQ2; t.bias = b + k * 512; TCG(t, 8192, 512); }
        // h_new = SQ2 * act @ P' - xk  (B = Pk)
        { TCP t = mkT();
          t.A0 = act; t.lda0 = 512; t.B0 = Pk; t.ldb0 = 512;
          t.C = (k == 7 ? yh + 3584 : hn); t.ldc = (k == 7 ? 4096 : 512);
          t.kChunks = 16; t.kSplitCh = 16;
          t.epi = 3; t.alpha = SQ2; t.S1 = xh + k * 512; t.ld1 = 4096;
          TCG(t, 8192, 512); }
        // yh[k-1] = hp - SQ2 * act @ G'  (B = Gk)
        { TCP t = mkT();
          t.A0 = act; t.lda0 = 512; t.B0 = Gk; t.ldb0 = 512;
          t.C = yh + (k - 1) * 512; t.ldc = 4096;
          t.kChunks = 16; t.kSplitCh = 16;
          t.epi = 4; t.alpha = SQ2; t.S1 = hp; t.ld1 = 512;
          TCG(t, 8192, 512); }
    }

    // out = 0.5*SQG * yh @ Q + 5.05 * x + by   (B = QmT)
    { TCP t = mkT();
      t.A0 = yh; t.lda0 = 4096; t.B0 = QmT; t.ldb0 = 4096;
      t.C = out; t.ldc = 1024; t.kChunks = 128; t.kSplitCh = 128;
      t.epi = 5; t.alpha = 0.5f * SQG; t.c1 = 0.5f * (0.1f + 10.0f);
      t.S1 = x; t.ld1 = 1024; t.bias = by; TCG(t, 8192, 1024); }
}